// round 2
// baseline (speedup 1.0000x reference)
#include <cuda_runtime.h>
#include <math.h>

// Problem constants
#define BB   8
#define CC   128
#define NN   4096
#define NLAB 16

#define BM 128
#define BN 128
// dynamic smem: As[128][128] + Bs[128][128] floats + 128 col labels
#define SMEM_BYTES (2 * BM * CC * 4 + BN * 4)

// Scratch (device globals — no allocation allowed)
__device__ float g_v[BB * CC * NN];     // normalized features, [b][c][n]
__device__ float g_pos[BB * NN];        // sum of exp(sim) over same-label j
__device__ float g_tot[BB * NN];        // sum of exp(sim) over all j != i
__device__ int   g_lab[BB * NN];
__device__ int   g_cnt[BB * NLAB];

// ---------------------------------------------------------------------------
// Kernel A: copy labels (int32!) + per-cloud label histogram
// ---------------------------------------------------------------------------
__global__ void k_labels(const int* __restrict__ labels) {
    __shared__ int hist[NLAB];
    int b = blockIdx.x;
    if (threadIdx.x < NLAB) hist[threadIdx.x] = 0;
    __syncthreads();
    for (int n = threadIdx.x; n < NN; n += blockDim.x) {
        int l = labels[b * NN + n];
        g_lab[b * NN + n] = l;
        atomicAdd(&hist[l], 1);
    }
    __syncthreads();
    if (threadIdx.x < NLAB) g_cnt[b * NLAB + threadIdx.x] = hist[threadIdx.x];
}

// ---------------------------------------------------------------------------
// Kernel B: L2-normalize each point (column of [C,N]); keep [b][c][n] layout
// ---------------------------------------------------------------------------
__global__ void k_norm(const float* __restrict__ f) {
    int b = blockIdx.y;
    int n = blockIdx.x * blockDim.x + threadIdx.x;
    const float* fb = f + (size_t)b * CC * NN;
    float ss = 0.f;
#pragma unroll 8
    for (int c = 0; c < CC; c++) {
        float x = fb[c * NN + n];
        ss = fmaf(x, x, ss);
    }
    float rinv = 1.0f / fmaxf(sqrtf(ss), 1e-12f);
    float* vb = g_v + (size_t)b * CC * NN;
#pragma unroll 8
    for (int c = 0; c < CC; c++) {
        vb[c * NN + n] = fb[c * NN + n] * rinv;
    }
}

// ---------------------------------------------------------------------------
// Kernel C: fused Gram + exp + masked row-sums.
// Grid: (NN/BM row-tiles, BB clouds). Block: 256 threads, 8x8 micro-tile.
// As[k][i] persistent for the block's 128 rows; Bs[k][j] streamed over j-tiles.
// ---------------------------------------------------------------------------
__global__ __launch_bounds__(256, 1) void k_gram() {
    extern __shared__ float smem[];
    float* As = smem;                    // [CC][BM]
    float* Bs = smem + BM * CC;          // [CC][BN]
    int*   labj = (int*)(smem + 2 * BM * CC);

    const int b  = blockIdx.y;
    const int i0 = blockIdx.x * BM;
    const int tid = threadIdx.x;
    const int tx = tid & 15;
    const int ty = tid >> 4;

    const float* vb = g_v + (size_t)b * CC * NN;

    // Load As: 128x128 floats = 4096 float4, 16 per thread. Coalesced per k-row.
#pragma unroll
    for (int t = 0; t < 16; t++) {
        int lin = tid + t * 256;          // float4 index
        int k   = lin >> 5;               // 32 float4 per k-row
        int i4  = (lin & 31) << 2;
        float4 val = *(const float4*)(vb + k * NN + i0 + i4);
        *(float4*)(As + k * BM + i4) = val;
    }

    int rl[8];
#pragma unroll
    for (int r = 0; r < 8; r++) rl[r] = g_lab[b * NN + i0 + ty * 8 + r];

    float pos[8], tot[8];
#pragma unroll
    for (int r = 0; r < 8; r++) { pos[r] = 0.f; tot[r] = 0.f; }

    __syncthreads();

    for (int jt = 0; jt < NN / BN; jt++) {
        const int j0 = jt * BN;
        // Load Bs tile + column labels
#pragma unroll
        for (int t = 0; t < 16; t++) {
            int lin = tid + t * 256;
            int k   = lin >> 5;
            int j4  = (lin & 31) << 2;
            float4 val = *(const float4*)(vb + k * NN + j0 + j4);
            *(float4*)(Bs + k * BN + j4) = val;
        }
        if (tid < BN) labj[tid] = g_lab[b * NN + j0 + tid];
        __syncthreads();

        float acc[8][8];
#pragma unroll
        for (int r = 0; r < 8; r++)
#pragma unroll
            for (int c = 0; c < 8; c++) acc[r][c] = 0.f;

#pragma unroll 4
        for (int k = 0; k < CC; k++) {
            float4 a0 = *(float4*)(As + k * BM + ty * 8);
            float4 a1 = *(float4*)(As + k * BM + ty * 8 + 4);
            float4 b0 = *(float4*)(Bs + k * BN + tx * 8);
            float4 b1 = *(float4*)(Bs + k * BN + tx * 8 + 4);
            float a[8] = {a0.x, a0.y, a0.z, a0.w, a1.x, a1.y, a1.z, a1.w};
            float bv[8] = {b0.x, b0.y, b0.z, b0.w, b1.x, b1.y, b1.z, b1.w};
#pragma unroll
            for (int r = 0; r < 8; r++)
#pragma unroll
                for (int c = 0; c < 8; c++)
                    acc[r][c] = fmaf(a[r], bv[c], acc[r][c]);
        }

        // Fused epilogue: exp + masked accumulation (TEMP cancels in the ratio)
#pragma unroll
        for (int r = 0; r < 8; r++) {
            int gi = i0 + ty * 8 + r;
#pragma unroll
            for (int c = 0; c < 8; c++) {
                int gj = j0 + tx * 8 + c;
                float e = __expf(acc[r][c]);
                if (gi != gj) {
                    tot[r] += e;
                    if (rl[r] == labj[tx * 8 + c]) pos[r] += e;
                }
            }
        }
        __syncthreads();   // before next tile overwrites Bs/labj
    }

    // Cross-thread (tx) reduction of the 8 row partials. Reuse As/Bs space.
    float* rpos = As;   // [128][16]
    float* rtot = Bs;   // [128][16]
#pragma unroll
    for (int r = 0; r < 8; r++) {
        rpos[(ty * 8 + r) * 16 + tx] = pos[r];
        rtot[(ty * 8 + r) * 16 + tx] = tot[r];
    }
    __syncthreads();
    if (tid < BM) {
        float sp = 0.f, st = 0.f;
#pragma unroll
        for (int x = 0; x < 16; x++) {
            sp += rpos[tid * 16 + x];
            st += rtot[tid * 16 + x];
        }
        g_pos[b * NN + i0 + tid] = sp;
        g_tot[b * NN + i0 + tid] = st;
    }
}

// ---------------------------------------------------------------------------
// Kernel D: final loss = mean over (b, i) of -log(pos / (pos + neg))
// ---------------------------------------------------------------------------
__global__ void k_loss(float* __restrict__ out) {
    __shared__ float red[1024];
    float s = 0.f;
    for (int i = threadIdx.x; i < BB * NN; i += blockDim.x) {
        int b = i >> 12;
        int l = g_lab[i];
        int cnt = g_cnt[b * NLAB + l];
        float pos = g_pos[i] / (float)cnt;
        float neg = (g_tot[i] - g_pos[i]) / (float)(NN - cnt);
        s += -logf(pos / (pos + neg));
    }
    red[threadIdx.x] = s;
    __syncthreads();
    for (int o = 512; o > 0; o >>= 1) {
        if (threadIdx.x < o) red[threadIdx.x] += red[threadIdx.x + o];
        __syncthreads();
    }
    if (threadIdx.x == 0) out[0] = red[0] / (float)(BB * NN);
}

// ---------------------------------------------------------------------------
extern "C" void kernel_launch(void* const* d_in, const int* in_sizes, int n_in,
                              void* d_out, int out_size) {
    const float* f   = (const float*)d_in[0];
    const int*   lab = (const int*)d_in[1];   // labels are int32 (JAX x64 off)
    float*       out = (float*)d_out;

    cudaFuncSetAttribute(k_gram, cudaFuncAttributeMaxDynamicSharedMemorySize,
                         SMEM_BYTES);

    k_labels<<<BB, 256>>>(lab);
    k_norm<<<dim3(NN / 256, BB), 256>>>(f);
    k_gram<<<dim3(NN / BM, BB), 256, SMEM_BYTES>>>();
    k_loss<<<1, 1024>>>(out);
}

// round 4
// speedup vs baseline: 3.0407x; 3.0407x over previous
#include <cuda_runtime.h>
#include <cuda_bf16.h>
#include <math.h>
#include <stdint.h>

#define BB   8
#define CC   128
#define NN   4096
#define NLAB 16

// ---------------------------------------------------------------------------
// Device scratch (no allocations allowed)
// ---------------------------------------------------------------------------
__device__ __nv_bfloat16 g_vt[BB * NN * CC];   // normalized, transposed [b][n][c]
__device__ unsigned char g_lab8[BB * NN];
__device__ int           g_cnt[BB * NLAB];
__device__ float         g_row[BB * NN];       // per-row loss terms

// ---------------------------------------------------------------------------
// smem layout for k_gram (all byte offsets from dynamic smem base)
// Tile: 128 rows x 256B (128 bf16 channels), padded to 272B/row (bank-safe)
// ---------------------------------------------------------------------------
#define ROWB   272
#define TILEB  (128 * ROWB)          // 34816
#define SM_A   0
#define SM_B0  TILEB
#define SM_B1  (2 * TILEB)
#define SM_LAB (3 * TILEB)           // 104448, 4096 bytes
#define SM_SP  (SM_LAB + 4096)       // 2 x 128 floats
#define SM_ST  (SM_SP + 1024)
#define SMEM_DYN (SM_ST + 1024)      // 110592 bytes

// ---------------------------------------------------------------------------
// PTX helpers (all plain sm_80+ features; no 'a' target needed)
// ---------------------------------------------------------------------------
__device__ __forceinline__ uint32_t s2u(const void* p) {
    return (uint32_t)__cvta_generic_to_shared(p);
}
__device__ __forceinline__ void cp16(uint32_t dst, const void* src) {
    asm volatile("cp.async.cg.shared.global [%0], [%1], 16;" :: "r"(dst), "l"(src) : "memory");
}
__device__ __forceinline__ void cp_commit() { asm volatile("cp.async.commit_group;" ::: "memory"); }
__device__ __forceinline__ void cp_wait0()  { asm volatile("cp.async.wait_group 0;" ::: "memory"); }

__device__ __forceinline__ void ldsm4(uint32_t* r, uint32_t addr) {
    asm volatile("ldmatrix.sync.aligned.m8n8.x4.shared.b16 {%0,%1,%2,%3}, [%4];"
                 : "=r"(r[0]), "=r"(r[1]), "=r"(r[2]), "=r"(r[3]) : "r"(addr));
}
__device__ __forceinline__ void mma16816(float* c, const uint32_t* a,
                                         uint32_t b0, uint32_t b1) {
    asm volatile(
        "mma.sync.aligned.m16n8k16.row.col.f32.bf16.bf16.f32 "
        "{%0,%1,%2,%3}, {%4,%5,%6,%7}, {%8,%9}, {%0,%1,%2,%3};"
        : "+f"(c[0]), "+f"(c[1]), "+f"(c[2]), "+f"(c[3])
        : "r"(a[0]), "r"(a[1]), "r"(a[2]), "r"(a[3]), "r"(b0), "r"(b1));
}

// ---------------------------------------------------------------------------
// Kernel A: labels -> uint8 copy + per-cloud histogram
// ---------------------------------------------------------------------------
__global__ void k_labels(const int* __restrict__ labels) {
    __shared__ int hist[NLAB];
    int b = blockIdx.x;
    if (threadIdx.x < NLAB) hist[threadIdx.x] = 0;
    __syncthreads();
    for (int n = threadIdx.x; n < NN; n += blockDim.x) {
        int l = labels[b * NN + n];
        g_lab8[b * NN + n] = (unsigned char)l;
        atomicAdd(&hist[l], 1);
    }
    __syncthreads();
    if (threadIdx.x < NLAB) g_cnt[b * NLAB + threadIdx.x] = hist[threadIdx.x];
}

// ---------------------------------------------------------------------------
// Kernel B: normalize + transpose + bf16 convert: g_vt[b][n][c]
// ---------------------------------------------------------------------------
__global__ void k_norm(const float* __restrict__ f) {
    extern __shared__ float ts[];               // [128][129] + rinv[128]
    float* rinv = ts + 128 * 129;
    int b = blockIdx.y, n0 = blockIdx.x * 128;
    const float* fb = f + (size_t)b * CC * NN;
    for (int idx = threadIdx.x; idx < 128 * 128; idx += 256) {
        int k = idx >> 7, n = idx & 127;
        ts[n * 129 + k] = fb[k * NN + n0 + n];
    }
    __syncthreads();
    if (threadIdx.x < 128) {
        float ss = 0.f;
#pragma unroll 8
        for (int k = 0; k < 128; k++) {
            float x = ts[threadIdx.x * 129 + k];
            ss = fmaf(x, x, ss);
        }
        rinv[threadIdx.x] = 1.0f / fmaxf(sqrtf(ss), 1e-12f);
    }
    __syncthreads();
    __nv_bfloat162* o2 = (__nv_bfloat162*)g_vt;
    for (int idx = threadIdx.x; idx < 128 * 64; idx += 256) {
        int n = idx >> 6, c2 = idx & 63;
        float r = rinv[n];
        float v0 = ts[n * 129 + 2 * c2] * r;
        float v1 = ts[n * 129 + 2 * c2 + 1] * r;
        o2[((size_t)b * NN + n0 + n) * 64 + c2] = __floats2bfloat162_rn(v0, v1);
    }
}

// ---------------------------------------------------------------------------
// Kernel C: HMMA (mma.sync bf16) Gram + fused exp + masked row-sums.
// 256 threads = 8 warps as 4(row) x 2(col). Warp tile 32x64.
// ---------------------------------------------------------------------------
__global__ __launch_bounds__(256, 1) void k_gram() {
    extern __shared__ char sm[];
    const uint32_t sb = s2u(sm);
    unsigned char* lab8s = (unsigned char*)(sm + SM_LAB);
    float* sp = (float*)(sm + SM_SP);
    float* st = (float*)(sm + SM_ST);

    const int b    = blockIdx.y;
    const int i0   = blockIdx.x * 128;
    const int tid  = threadIdx.x;
    const int wid  = tid >> 5;
    const int lane = tid & 31;
    const int wm   = wid & 3;          // warp row: rows wm*32..+31
    const int wn   = wid >> 2;         // warp col: cols wn*64..+63

    const __nv_bfloat16* vt = g_vt + (size_t)b * NN * CC;

    // --- prologue: load A tile (rows i0..), B tile 0 (rows 0..), labels ---
#pragma unroll
    for (int t = 0; t < 8; t++) {
        int idx = tid + t * 256;              // 2048 chunks of 16B
        int row = idx >> 4, c16 = idx & 15;
        cp16(sb + SM_A + row * ROWB + c16 * 16,
             vt + (size_t)(i0 + row) * CC + c16 * 8);
    }
#pragma unroll
    for (int t = 0; t < 8; t++) {
        int idx = tid + t * 256;
        int row = idx >> 4, c16 = idx & 15;
        cp16(sb + SM_B0 + row * ROWB + c16 * 16,
             vt + (size_t)row * CC + c16 * 8);
    }
    cp16(sb + SM_LAB + tid * 16, g_lab8 + (size_t)b * NN + tid * 16);
    cp_commit();
    cp_wait0();
    __syncthreads();

    // row labels for this lane's 4 accumulated rows: (mt, upper8) in {0,1}^2
    int rl[2][2];
#pragma unroll
    for (int mt = 0; mt < 2; mt++)
#pragma unroll
        for (int u = 0; u < 2; u++)
            rl[mt][u] = (int)lab8s[i0 + wm * 32 + mt * 16 + (lane >> 2) + u * 8];

    float pos[2][2] = {{0.f, 0.f}, {0.f, 0.f}};
    float tot[2][2] = {{0.f, 0.f}, {0.f, 0.f}};

    // ldmatrix lane addressing (shared by A and B): row = base + (lane&15),
    // k-offset = k0 + (lane>>4)*8 elements
    const int lrow = lane & 15;
    const int lkof = (lane >> 4) << 3;

    for (int jt = 0; jt < 32; jt++) {
        const int cur = jt & 1;
        // prefetch next B tile into the other buffer
        if (jt + 1 < 32) {
            const int j0n = (jt + 1) * 128;
            uint32_t bdst = sb + (cur ? SM_B0 : SM_B1);
#pragma unroll
            for (int t = 0; t < 8; t++) {
                int idx = tid + t * 256;
                int row = idx >> 4, c16 = idx & 15;
                cp16(bdst + row * ROWB + c16 * 16,
                     vt + (size_t)(j0n + row) * CC + c16 * 8);
            }
            cp_commit();
        }

        const uint32_t aB = sb + SM_A;
        const uint32_t bB = sb + (cur ? SM_B1 : SM_B0);

        float acc[2][8][4];
#pragma unroll
        for (int mt = 0; mt < 2; mt++)
#pragma unroll
            for (int nt = 0; nt < 8; nt++)
#pragma unroll
                for (int r = 0; r < 4; r++) acc[mt][nt][r] = 0.f;

#pragma unroll
        for (int ks = 0; ks < 8; ks++) {
            const int k0 = ks * 16;
            uint32_t a[2][4], bq[4][4];
#pragma unroll
            for (int mt = 0; mt < 2; mt++) {
                int row = wm * 32 + mt * 16 + lrow;
                ldsm4(a[mt], aB + row * ROWB + (k0 + lkof) * 2);
            }
#pragma unroll
            for (int q = 0; q < 4; q++) {
                int row = wn * 64 + q * 16 + lrow;
                ldsm4(bq[q], bB + row * ROWB + (k0 + lkof) * 2);
            }
#pragma unroll
            for (int mt = 0; mt < 2; mt++)
#pragma unroll
                for (int q = 0; q < 4; q++) {
                    mma16816(acc[mt][2 * q],     a[mt], bq[q][0], bq[q][2]);
                    mma16816(acc[mt][2 * q + 1], a[mt], bq[q][1], bq[q][3]);
                }
        }

        // --- fused epilogue on register fragments ---
        const int j0 = jt * 128;
        // column labels this lane touches: nt*8 + (lane&3)*2 + {0,1}
        int cl0[8], cl1[8];
#pragma unroll
        for (int nt = 0; nt < 8; nt++) {
            int jj = j0 + wn * 64 + nt * 8 + (lane & 3) * 2;
            cl0[nt] = (int)lab8s[jj];
            cl1[nt] = (int)lab8s[jj + 1];
        }
#pragma unroll
        for (int mt = 0; mt < 2; mt++)
#pragma unroll
            for (int u = 0; u < 2; u++) {
                const int gi = i0 + wm * 32 + mt * 16 + (lane >> 2) + u * 8;
                const int rlab = rl[mt][u];
                float tsum = 0.f, psum = 0.f;
#pragma unroll
                for (int nt = 0; nt < 8; nt++) {
                    const int gj = j0 + wn * 64 + nt * 8 + (lane & 3) * 2;
                    float e0 = __expf(acc[mt][nt][2 * u]);
                    float e1 = __expf(acc[mt][nt][2 * u + 1]);
                    if (gi == gj)     e0 = 0.f;
                    if (gi == gj + 1) e1 = 0.f;
                    tsum += e0 + e1;
                    if (cl0[nt] == rlab) psum += e0;
                    if (cl1[nt] == rlab) psum += e1;
                }
                tot[mt][u] += tsum;
                pos[mt][u] += psum;
            }

        cp_wait0();
        __syncthreads();   // prefetched tile visible; safe to overwrite next iter
    }

    // --- reduce across the 4 lanes of each row quad, then across wn halves ---
#pragma unroll
    for (int mt = 0; mt < 2; mt++)
#pragma unroll
        for (int u = 0; u < 2; u++) {
            float p = pos[mt][u], t = tot[mt][u];
            p += __shfl_xor_sync(0xFFFFFFFF, p, 1);
            p += __shfl_xor_sync(0xFFFFFFFF, p, 2);
            t += __shfl_xor_sync(0xFFFFFFFF, t, 1);
            t += __shfl_xor_sync(0xFFFFFFFF, t, 2);
            if ((lane & 3) == 0) {
                int row = wm * 32 + mt * 16 + (lane >> 2) + u * 8;
                sp[wn * 128 + row] = p;
                st[wn * 128 + row] = t;
            }
        }
    __syncthreads();

    if (tid < 128) {
        float p = sp[tid] + sp[128 + tid];
        float t = st[tid] + st[128 + tid];
        int l = (int)lab8s[i0 + tid];
        int cnt = g_cnt[b * NLAB + l];
        float pm = p / (float)cnt;
        float nm = (t - p) / (float)(NN - cnt);
        g_row[b * NN + i0 + tid] = __logf((pm + nm) / pm);
    }
}

// ---------------------------------------------------------------------------
// Kernel D: mean of per-row terms
// ---------------------------------------------------------------------------
__global__ void k_loss(float* __restrict__ out) {
    __shared__ float red[1024];
    float s = 0.f;
    for (int i = threadIdx.x; i < BB * NN; i += 1024) s += g_row[i];
    red[threadIdx.x] = s;
    __syncthreads();
    for (int o = 512; o > 0; o >>= 1) {
        if (threadIdx.x < o) red[threadIdx.x] += red[threadIdx.x + o];
        __syncthreads();
    }
    if (threadIdx.x == 0) out[0] = red[0] / (float)(BB * NN);
}

// ---------------------------------------------------------------------------
extern "C" void kernel_launch(void* const* d_in, const int* in_sizes, int n_in,
                              void* d_out, int out_size) {
    const float* f   = (const float*)d_in[0];
    const int*   lab = (const int*)d_in[1];
    float*       out = (float*)d_out;

    cudaFuncSetAttribute(k_norm, cudaFuncAttributeMaxDynamicSharedMemorySize,
                         (128 * 129 + 128) * 4);
    cudaFuncSetAttribute(k_gram, cudaFuncAttributeMaxDynamicSharedMemorySize,
                         SMEM_DYN);

    k_labels<<<BB, 256>>>(lab);
    k_norm<<<dim3(NN / 128, BB), 256, (128 * 129 + 128) * 4>>>(f);
    k_gram<<<dim3(NN / 128, BB), 256, SMEM_DYN>>>();
    k_loss<<<1, 1024>>>(out);
}

// round 5
// speedup vs baseline: 5.1873x; 1.7060x over previous
#include <cuda_runtime.h>
#include <cuda_bf16.h>
#include <math.h>
#include <stdint.h>

#define BB   8
#define CC   128
#define NN   4096
#define NLAB 16

// ---------------------------------------------------------------------------
// Device scratch (no allocations allowed)
// ---------------------------------------------------------------------------
__device__ __nv_bfloat16 g_vt[BB * NN * CC];   // normalized, transposed [b][n][c]
__device__ unsigned char g_lab8[BB * NN];
__device__ int           g_cnt[BB * NLAB];
__device__ float         g_part[BB * (NN / 128)];   // per-CTA loss partials

// ---------------------------------------------------------------------------
// smem layout for k_gram. Tile rows padded to 272B (conflict-free LDSM).
// ---------------------------------------------------------------------------
#define ROWB   272
#define TILEB  (128 * ROWB)          // 34816
#define SM_A   0
#define SM_B0  TILEB
#define SM_B1  (2 * TILEB)
#define SM_LAB (3 * TILEB)           // 4096 bytes
#define SM_SP  (SM_LAB + 4096)       // 2 x 128 floats
#define SM_ST  (SM_SP + 1024)
#define SMEM_DYN (SM_ST + 1024)      // 110592 bytes -> 2 CTAs/SM fit in 228KB

// ---------------------------------------------------------------------------
// PTX helpers (plain sm_80+ features)
// ---------------------------------------------------------------------------
__device__ __forceinline__ uint32_t s2u(const void* p) {
    return (uint32_t)__cvta_generic_to_shared(p);
}
__device__ __forceinline__ void cp16(uint32_t dst, const void* src) {
    asm volatile("cp.async.cg.shared.global [%0], [%1], 16;" :: "r"(dst), "l"(src) : "memory");
}
__device__ __forceinline__ void cp_commit() { asm volatile("cp.async.commit_group;" ::: "memory"); }
__device__ __forceinline__ void cp_wait0()  { asm volatile("cp.async.wait_group 0;" ::: "memory"); }

__device__ __forceinline__ void ldsm4(uint32_t* r, uint32_t addr) {
    asm volatile("ldmatrix.sync.aligned.m8n8.x4.shared.b16 {%0,%1,%2,%3}, [%4];"
                 : "=r"(r[0]), "=r"(r[1]), "=r"(r[2]), "=r"(r[3]) : "r"(addr));
}
__device__ __forceinline__ void mma16816(float* c, const uint32_t* a,
                                         uint32_t b0, uint32_t b1) {
    asm volatile(
        "mma.sync.aligned.m16n8k16.row.col.f32.bf16.bf16.f32 "
        "{%0,%1,%2,%3}, {%4,%5,%6,%7}, {%8,%9}, {%0,%1,%2,%3};"
        : "+f"(c[0]), "+f"(c[1]), "+f"(c[2]), "+f"(c[3])
        : "r"(a[0]), "r"(a[1]), "r"(a[2]), "r"(a[3]), "r"(b0), "r"(b1));
}

// ---------------------------------------------------------------------------
// Kernel A: labels -> uint8 copy + per-cloud histogram
// ---------------------------------------------------------------------------
__global__ void k_labels(const int* __restrict__ labels) {
    __shared__ int hist[NLAB];
    int b = blockIdx.x;
    if (threadIdx.x < NLAB) hist[threadIdx.x] = 0;
    __syncthreads();
    for (int n = threadIdx.x; n < NN; n += blockDim.x) {
        int l = labels[b * NN + n];
        g_lab8[b * NN + n] = (unsigned char)l;
        atomicAdd(&hist[l], 1);
    }
    __syncthreads();
    if (threadIdx.x < NLAB) g_cnt[b * NLAB + threadIdx.x] = hist[threadIdx.x];
}

// ---------------------------------------------------------------------------
// Kernel B: normalize + transpose + bf16 convert: g_vt[b][n][c]
// ---------------------------------------------------------------------------
__global__ void k_norm(const float* __restrict__ f) {
    extern __shared__ float ts[];               // [128][129] + rinv[128]
    float* rinv = ts + 128 * 129;
    int b = blockIdx.y, n0 = blockIdx.x * 128;
    const float* fb = f + (size_t)b * CC * NN;
    for (int idx = threadIdx.x; idx < 128 * 128; idx += 256) {
        int k = idx >> 7, n = idx & 127;
        ts[n * 129 + k] = fb[k * NN + n0 + n];
    }
    __syncthreads();
    if (threadIdx.x < 128) {
        float ss = 0.f;
#pragma unroll 8
        for (int k = 0; k < 128; k++) {
            float x = ts[threadIdx.x * 129 + k];
            ss = fmaf(x, x, ss);
        }
        rinv[threadIdx.x] = 1.0f / fmaxf(sqrtf(ss), 1e-12f);
    }
    __syncthreads();
    __nv_bfloat162* o2 = (__nv_bfloat162*)g_vt;
    for (int idx = threadIdx.x; idx < 128 * 64; idx += 256) {
        int n = idx >> 6, c2 = idx & 63;
        float r = rinv[n];
        float v0 = ts[n * 129 + 2 * c2] * r;
        float v1 = ts[n * 129 + 2 * c2 + 1] * r;
        o2[((size_t)b * NN + n0 + n) * 64 + c2] = __floats2bfloat162_rn(v0, v1);
    }
}

// ---------------------------------------------------------------------------
// Fused epilogue for one 32-col half of the warp strip.
// acc[mt][nt][4]: mt in {0,1} row sub-tiles, nt in {0,1,2,3} 8-col groups.
// ---------------------------------------------------------------------------
template <bool DIAG>
__device__ __forceinline__ void epi_half(
    const float acc[2][4][4], int j0w, int i_lane0, int lane,
    const int rl[2][2], const unsigned char* __restrict__ lab8s,
    float pos[2][2], float tot[2][2])
{
    int cl0[4], cl1[4];
#pragma unroll
    for (int nt = 0; nt < 4; nt++) {
        int jj = j0w + nt * 8 + (lane & 3) * 2;
        cl0[nt] = (int)lab8s[jj];
        cl1[nt] = (int)lab8s[jj + 1];
    }
#pragma unroll
    for (int mt = 0; mt < 2; mt++)
#pragma unroll
        for (int u = 0; u < 2; u++) {
            const int rlab = rl[mt][u];
            float tsum = 0.f, psum = 0.f;
#pragma unroll
            for (int nt = 0; nt < 4; nt++) {
                float e0 = __expf(acc[mt][nt][2 * u]);
                float e1 = __expf(acc[mt][nt][2 * u + 1]);
                if (DIAG) {
                    const int gi = i_lane0 + mt * 16 + u * 8;       // local row
                    const int gj = j0w + nt * 8 + (lane & 3) * 2;   // global col
                    // caller passes i_lane0 as GLOBAL row base when DIAG
                    if (gi == gj)     e0 = 0.f;
                    if (gi == gj + 1) e1 = 0.f;
                }
                tsum += e0 + e1;
                if (cl0[nt] == rlab) psum += e0;
                if (cl1[nt] == rlab) psum += e1;
            }
            tot[mt][u] += tsum;
            pos[mt][u] += psum;
        }
}

// ---------------------------------------------------------------------------
// Kernel C: HMMA Gram + fused exp + masked row-sums. 8 warps 4x2, occ 2.
// ---------------------------------------------------------------------------
__global__ __launch_bounds__(256, 2) void k_gram() {
    extern __shared__ char sm[];
    const uint32_t sb = s2u(sm);
    unsigned char* lab8s = (unsigned char*)(sm + SM_LAB);
    float* sp = (float*)(sm + SM_SP);
    float* st = (float*)(sm + SM_ST);

    const int b    = blockIdx.y;
    const int i0   = blockIdx.x * 128;
    const int tid  = threadIdx.x;
    const int wid  = tid >> 5;
    const int lane = tid & 31;
    const int wm   = wid & 3;          // warp row: rows wm*32..+31
    const int wn   = wid >> 2;         // warp col: cols wn*64..+63

    const __nv_bfloat16* vt = g_vt + (size_t)b * NN * CC;

    // --- prologue: A tile (rows i0..), B tile 0, labels ---
#pragma unroll
    for (int t = 0; t < 8; t++) {
        int idx = tid + t * 256;
        int row = idx >> 4, c16 = idx & 15;
        cp16(sb + SM_A + row * ROWB + c16 * 16,
             vt + (size_t)(i0 + row) * CC + c16 * 8);
    }
#pragma unroll
    for (int t = 0; t < 8; t++) {
        int idx = tid + t * 256;
        int row = idx >> 4, c16 = idx & 15;
        cp16(sb + SM_B0 + row * ROWB + c16 * 16,
             vt + (size_t)row * CC + c16 * 8);
    }
    cp16(sb + SM_LAB + tid * 16, g_lab8 + (size_t)b * NN + tid * 16);
    cp_commit();
    cp_wait0();
    __syncthreads();

    int rl[2][2];
#pragma unroll
    for (int mt = 0; mt < 2; mt++)
#pragma unroll
        for (int u = 0; u < 2; u++)
            rl[mt][u] = (int)lab8s[i0 + wm * 32 + mt * 16 + (lane >> 2) + u * 8];

    float pos[2][2] = {{0.f, 0.f}, {0.f, 0.f}};
    float tot[2][2] = {{0.f, 0.f}, {0.f, 0.f}};

    const int lrow = lane & 15;            // ldmatrix row within 16
    const int lkof = (lane >> 4) << 3;     // k offset 0 or 8

    for (int jt = 0; jt < 32; jt++) {
        const int cur = jt & 1;
        if (jt + 1 < 32) {
            const int j0n = (jt + 1) * 128;
            uint32_t bdst = sb + (cur ? SM_B0 : SM_B1);
#pragma unroll
            for (int t = 0; t < 8; t++) {
                int idx = tid + t * 256;
                int row = idx >> 4, c16 = idx & 15;
                cp16(bdst + row * ROWB + c16 * 16,
                     vt + (size_t)(j0n + row) * CC + c16 * 8);
            }
            cp_commit();
        }

        const uint32_t aB = sb + SM_A;
        const uint32_t bB = sb + (cur ? SM_B1 : SM_B0);
        const int j0 = jt * 128;
        const bool diag = (jt == blockIdx.x);

#pragma unroll
        for (int h = 0; h < 2; h++) {
            float acc[2][4][4];
#pragma unroll
            for (int mt = 0; mt < 2; mt++)
#pragma unroll
                for (int nt = 0; nt < 4; nt++)
#pragma unroll
                    for (int r = 0; r < 4; r++) acc[mt][nt][r] = 0.f;

#pragma unroll
            for (int ks = 0; ks < 8; ks++) {
                const int k0 = ks * 16;
                uint32_t a[2][4], bq[2][4];
#pragma unroll
                for (int mt = 0; mt < 2; mt++) {
                    int row = wm * 32 + mt * 16 + lrow;
                    ldsm4(a[mt], aB + row * ROWB + (k0 + lkof) * 2);
                }
#pragma unroll
                for (int q = 0; q < 2; q++) {
                    int row = wn * 64 + h * 32 + q * 16 + lrow;
                    ldsm4(bq[q], bB + row * ROWB + (k0 + lkof) * 2);
                }
#pragma unroll
                for (int mt = 0; mt < 2; mt++)
#pragma unroll
                    for (int q = 0; q < 2; q++) {
                        mma16816(acc[mt][2 * q],     a[mt], bq[q][0], bq[q][2]);
                        mma16816(acc[mt][2 * q + 1], a[mt], bq[q][1], bq[q][3]);
                    }
            }

            const int j0w = j0 + wn * 64 + h * 32;   // global col base (half)
            if (diag) {
                const int gi_base = i0 + wm * 32 + (lane >> 2);
                epi_half<true>(acc, j0w, gi_base, lane, rl, lab8s, pos, tot);
            } else {
                epi_half<false>(acc, j0w, 0, lane, rl, lab8s, pos, tot);
            }
        }

        cp_wait0();
        __syncthreads();
    }

    // --- lane-quad reduce, col-half combine, per-row loss, CTA partial ---
#pragma unroll
    for (int mt = 0; mt < 2; mt++)
#pragma unroll
        for (int u = 0; u < 2; u++) {
            float p = pos[mt][u], t = tot[mt][u];
            p += __shfl_xor_sync(0xFFFFFFFF, p, 1);
            p += __shfl_xor_sync(0xFFFFFFFF, p, 2);
            t += __shfl_xor_sync(0xFFFFFFFF, t, 1);
            t += __shfl_xor_sync(0xFFFFFFFF, t, 2);
            if ((lane & 3) == 0) {
                int row = wm * 32 + mt * 16 + (lane >> 2) + u * 8;
                sp[wn * 128 + row] = p;
                st[wn * 128 + row] = t;
            }
        }
    __syncthreads();

    if (tid < 128) {
        float p = sp[tid] + sp[128 + tid];
        float t = st[tid] + st[128 + tid];
        int l = (int)lab8s[i0 + tid];
        int cnt = g_cnt[b * NLAB + l];
        float pm = p / (float)cnt;
        float nm = (t - p) / (float)(NN - cnt);
        sp[tid] = __logf((pm + nm) / pm);
    }
    __syncthreads();
    if (tid < 64) sp[tid] += sp[tid + 64];
    __syncthreads();
    if (tid < 32) {
        float v = sp[tid] + sp[tid + 32];
#pragma unroll
        for (int o = 16; o > 0; o >>= 1) v += __shfl_xor_sync(0xFFFFFFFF, v, o);
        if (tid == 0) g_part[b * 32 + blockIdx.x] = v;
    }
}

// ---------------------------------------------------------------------------
// Kernel D: sum 256 CTA partials -> mean
// ---------------------------------------------------------------------------
__global__ void k_loss(float* __restrict__ out) {
    __shared__ float red[256];
    int t = threadIdx.x;
    red[t] = g_part[t];
    __syncthreads();
    if (t < 128) red[t] += red[t + 128];
    __syncthreads();
    if (t < 64) red[t] += red[t + 64];
    __syncthreads();
    if (t < 32) {
        float v = red[t] + red[t + 32];
#pragma unroll
        for (int o = 16; o > 0; o >>= 1) v += __shfl_xor_sync(0xFFFFFFFF, v, o);
        if (t == 0) out[0] = v / (float)(BB * NN);
    }
}

// ---------------------------------------------------------------------------
extern "C" void kernel_launch(void* const* d_in, const int* in_sizes, int n_in,
                              void* d_out, int out_size) {
    const float* f   = (const float*)d_in[0];
    const int*   lab = (const int*)d_in[1];
    float*       out = (float*)d_out;

    cudaFuncSetAttribute(k_norm, cudaFuncAttributeMaxDynamicSharedMemorySize,
                         (128 * 129 + 128) * 4);
    cudaFuncSetAttribute(k_gram, cudaFuncAttributeMaxDynamicSharedMemorySize,
                         SMEM_DYN);

    k_labels<<<BB, 256>>>(lab);
    k_norm<<<dim3(NN / 128, BB), 256, (128 * 129 + 128) * 4>>>(f);
    k_gram<<<dim3(NN / 128, BB), 256, SMEM_DYN>>>();
    k_loss<<<1, 256>>>(out);
}

// round 6
// speedup vs baseline: 7.1174x; 1.3721x over previous
#include <cuda_runtime.h>
#include <cuda_bf16.h>
#include <math.h>
#include <stdint.h>

#define BB   8
#define CC   128
#define NN   4096
#define NLAB 16
#define NSLOT 18    // 0,1: own-row sums (wn=0/1); 2..17: col sums from source d=1..16

// ---------------------------------------------------------------------------
// Device scratch (no allocations allowed)
// ---------------------------------------------------------------------------
__device__ __nv_bfloat16 g_vt[BB * NN * CC];     // normalized (x sqrt(log2e)) [b][n][c]
__device__ unsigned char g_lab8[BB * NN];
__device__ int           g_cnt[BB * NLAB];
__device__ float2        g_stage[BB * 32 * NSLOT * 128];  // (pos, tot) partials
__device__ float         g_part[BB * 32];

// ---------------------------------------------------------------------------
// smem layout for k_gram. Tile rows padded to 272B (conflict-free LDSM).
// ---------------------------------------------------------------------------
#define ROWB   272
#define TILEB  (128 * ROWB)          // 34816
#define SM_A   0
#define SM_B0  TILEB
#define SM_B1  (2 * TILEB)
#define SM_LAB (3 * TILEB)           // 4096 B labels
#define SM_CS  (SM_LAB + 4096)       // 4096 B col partials [4 wm][128 col][2]
#define SMEM_DYN (SM_CS + 4096)      // 112640 B -> 2 CTAs/SM

// ---------------------------------------------------------------------------
// PTX helpers (plain sm_80+ features)
// ---------------------------------------------------------------------------
__device__ __forceinline__ uint32_t s2u(const void* p) {
    return (uint32_t)__cvta_generic_to_shared(p);
}
__device__ __forceinline__ void cp16(uint32_t dst, const void* src) {
    asm volatile("cp.async.cg.shared.global [%0], [%1], 16;" :: "r"(dst), "l"(src) : "memory");
}
__device__ __forceinline__ void cp_commit() { asm volatile("cp.async.commit_group;" ::: "memory"); }
__device__ __forceinline__ void cp_wait0()  { asm volatile("cp.async.wait_group 0;" ::: "memory"); }

__device__ __forceinline__ void ldsm4(uint32_t* r, uint32_t addr) {
    asm volatile("ldmatrix.sync.aligned.m8n8.x4.shared.b16 {%0,%1,%2,%3}, [%4];"
                 : "=r"(r[0]), "=r"(r[1]), "=r"(r[2]), "=r"(r[3]) : "r"(addr));
}
__device__ __forceinline__ void mma16816(float* c, const uint32_t* a,
                                         uint32_t b0, uint32_t b1) {
    asm volatile(
        "mma.sync.aligned.m16n8k16.row.col.f32.bf16.bf16.f32 "
        "{%0,%1,%2,%3}, {%4,%5,%6,%7}, {%8,%9}, {%0,%1,%2,%3};"
        : "+f"(c[0]), "+f"(c[1]), "+f"(c[2]), "+f"(c[3])
        : "r"(a[0]), "r"(a[1]), "r"(a[2]), "r"(a[3]), "r"(b0), "r"(b1));
}
__device__ __forceinline__ float ex2(float x) {
    float y; asm("ex2.approx.f32 %0, %1;" : "=f"(y) : "f"(x)); return y;
}

// ---------------------------------------------------------------------------
// Kernel A: labels -> uint8 copy + per-cloud histogram
// ---------------------------------------------------------------------------
__global__ void k_labels(const int* __restrict__ labels) {
    __shared__ int hist[NLAB];
    int b = blockIdx.x;
    if (threadIdx.x < NLAB) hist[threadIdx.x] = 0;
    __syncthreads();
    for (int n = threadIdx.x; n < NN; n += blockDim.x) {
        int l = labels[b * NN + n];
        g_lab8[b * NN + n] = (unsigned char)l;
        atomicAdd(&hist[l], 1);
    }
    __syncthreads();
    if (threadIdx.x < NLAB) g_cnt[b * NLAB + threadIdx.x] = hist[threadIdx.x];
}

// ---------------------------------------------------------------------------
// Kernel B: normalize (x sqrt(log2e)) + transpose + bf16: g_vt[b][n][c]
// Gram then yields sim*log2(e), so epilogue exp is a bare ex2.
// ---------------------------------------------------------------------------
__global__ void k_norm(const float* __restrict__ f) {
    extern __shared__ float ts[];               // [128][129] + rinv[128]
    float* rinv = ts + 128 * 129;
    int b = blockIdx.y, n0 = blockIdx.x * 128;
    const float* fb = f + (size_t)b * CC * NN;
    for (int idx = threadIdx.x; idx < 128 * 128; idx += 256) {
        int k = idx >> 7, n = idx & 127;
        ts[n * 129 + k] = fb[k * NN + n0 + n];
    }
    __syncthreads();
    if (threadIdx.x < 128) {
        float ss = 0.f;
#pragma unroll 8
        for (int k = 0; k < 128; k++) {
            float x = ts[threadIdx.x * 129 + k];
            ss = fmaf(x, x, ss);
        }
        // sqrt(log2(e)) folded into the normalization
        rinv[threadIdx.x] = 1.2011224087864498f / fmaxf(sqrtf(ss), 1e-12f);
    }
    __syncthreads();
    __nv_bfloat162* o2 = (__nv_bfloat162*)g_vt;
    for (int idx = threadIdx.x; idx < 128 * 64; idx += 256) {
        int n = idx >> 6, c2 = idx & 63;
        float r = rinv[n];
        float v0 = ts[n * 129 + 2 * c2] * r;
        float v1 = ts[n * 129 + 2 * c2 + 1] * r;
        o2[((size_t)b * NN + n0 + n) * 64 + c2] = __floats2bfloat162_rn(v0, v1);
    }
}

// ---------------------------------------------------------------------------
// One 128x128 tile: MMA + exp + row sums (registers) + col sums (scol).
// ---------------------------------------------------------------------------
template <bool DIAG>
__device__ __forceinline__ void do_tile(
    uint32_t aB, uint32_t bB, int i0, int j0,
    int wm, int wn, int lane,
    const int rl[2][2], const unsigned char* __restrict__ lab8s,
    float pos[2][2], float tot[2][2], float* scol)
{
    const int lrow = lane & 15;
    const int lkof = (lane >> 4) << 3;

#pragma unroll
    for (int h = 0; h < 2; h++) {
        float acc[2][4][4];
#pragma unroll
        for (int mt = 0; mt < 2; mt++)
#pragma unroll
            for (int nt = 0; nt < 4; nt++)
#pragma unroll
                for (int r = 0; r < 4; r++) acc[mt][nt][r] = 0.f;

#pragma unroll
        for (int ks = 0; ks < 8; ks++) {
            const int k0 = ks * 16;
            uint32_t a[2][4], bq[2][4];
#pragma unroll
            for (int mt = 0; mt < 2; mt++) {
                int row = wm * 32 + mt * 16 + lrow;
                ldsm4(a[mt], aB + row * ROWB + (k0 + lkof) * 2);
            }
#pragma unroll
            for (int q = 0; q < 2; q++) {
                int row = wn * 64 + h * 32 + q * 16 + lrow;
                ldsm4(bq[q], bB + row * ROWB + (k0 + lkof) * 2);
            }
#pragma unroll
            for (int mt = 0; mt < 2; mt++)
#pragma unroll
                for (int q = 0; q < 2; q++) {
                    mma16816(acc[mt][2 * q],     a[mt], bq[q][0], bq[q][2]);
                    mma16816(acc[mt][2 * q + 1], a[mt], bq[q][1], bq[q][3]);
                }
        }

        // column labels for this lane (global)
        int cl0[4], cl1[4];
#pragma unroll
        for (int nt = 0; nt < 4; nt++) {
            int jj = j0 + wn * 64 + h * 32 + nt * 8 + (lane & 3) * 2;
            cl0[nt] = (int)lab8s[jj];
            cl1[nt] = (int)lab8s[jj + 1];
        }

        float cpos[4][2], ctot[4][2];
        if (!DIAG) {
#pragma unroll
            for (int nt = 0; nt < 4; nt++) {
                cpos[nt][0] = cpos[nt][1] = 0.f;
                ctot[nt][0] = ctot[nt][1] = 0.f;
            }
        }

#pragma unroll
        for (int mt = 0; mt < 2; mt++)
#pragma unroll
            for (int u = 0; u < 2; u++) {
                const int rlab = rl[mt][u];
                float tsum = 0.f, psum = 0.f;
#pragma unroll
                for (int nt = 0; nt < 4; nt++) {
                    float e0 = ex2(acc[mt][nt][2 * u]);
                    float e1 = ex2(acc[mt][nt][2 * u + 1]);
                    if (DIAG) {
                        const int gi = i0 + wm * 32 + mt * 16 + (lane >> 2) + u * 8;
                        const int gj = j0 + wn * 64 + h * 32 + nt * 8 + (lane & 3) * 2;
                        if (gi == gj)     e0 = 0.f;
                        if (gi == gj + 1) e1 = 0.f;
                    }
                    const bool m0 = (cl0[nt] == rlab);
                    const bool m1 = (cl1[nt] == rlab);
                    tsum += e0 + e1;
                    if (m0) psum += e0;
                    if (m1) psum += e1;
                    if (!DIAG) {
                        ctot[nt][0] += e0;
                        ctot[nt][1] += e1;
                        if (m0) cpos[nt][0] += e0;
                        if (m1) cpos[nt][1] += e1;
                    }
                }
                tot[mt][u] += tsum;
                pos[mt][u] += psum;
            }

        if (!DIAG) {
            // reduce col partials over the 8 lanes sharing (lane&3)
#pragma unroll
            for (int nt = 0; nt < 4; nt++)
#pragma unroll
                for (int e = 0; e < 2; e++) {
                    float cp = cpos[nt][e], ct = ctot[nt][e];
                    cp += __shfl_xor_sync(0xFFFFFFFF, cp, 4);
                    cp += __shfl_xor_sync(0xFFFFFFFF, cp, 8);
                    cp += __shfl_xor_sync(0xFFFFFFFF, cp, 16);
                    ct += __shfl_xor_sync(0xFFFFFFFF, ct, 4);
                    ct += __shfl_xor_sync(0xFFFFFFFF, ct, 8);
                    ct += __shfl_xor_sync(0xFFFFFFFF, ct, 16);
                    if (lane < 4) {
                        int col = wn * 64 + h * 32 + nt * 8 + lane * 2 + e;
                        scol[(wm * 128 + col) * 2 + 0] = cp;
                        scol[(wm * 128 + col) * 2 + 1] = ct;
                    }
                }
        }
    }
}

// ---------------------------------------------------------------------------
// Kernel C: symmetric HMMA Gram. CTA it streams jt=(it+d)&31, d=0..15/16.
// ---------------------------------------------------------------------------
__global__ __launch_bounds__(256, 2) void k_gram() {
    extern __shared__ char sm[];
    const uint32_t sb = s2u(sm);
    unsigned char* lab8s = (unsigned char*)(sm + SM_LAB);
    float* scol = (float*)(sm + SM_CS);

    const int b    = blockIdx.y;
    const int it   = blockIdx.x;
    const int i0   = it * 128;
    const int tid  = threadIdx.x;
    const int wid  = tid >> 5;
    const int lane = tid & 31;
    const int wm   = wid & 3;
    const int wn   = wid >> 2;
    const int npair = (it < 16) ? 17 : 16;

    const __nv_bfloat16* vt = g_vt + (size_t)b * NN * CC;

    // prologue: A = rows i0, B0 = rows i0 (d=0 diag tile), labels
#pragma unroll
    for (int t = 0; t < 8; t++) {
        int idx = tid + t * 256;
        int row = idx >> 4, c16 = idx & 15;
        cp16(sb + SM_A + row * ROWB + c16 * 16,
             vt + (size_t)(i0 + row) * CC + c16 * 8);
        cp16(sb + SM_B0 + row * ROWB + c16 * 16,
             vt + (size_t)(i0 + row) * CC + c16 * 8);
    }
    cp16(sb + SM_LAB + tid * 16, g_lab8 + (size_t)b * NN + tid * 16);
    cp_commit();
    cp_wait0();
    __syncthreads();

    int rl[2][2];
#pragma unroll
    for (int mt = 0; mt < 2; mt++)
#pragma unroll
        for (int u = 0; u < 2; u++)
            rl[mt][u] = (int)lab8s[i0 + wm * 32 + mt * 16 + (lane >> 2) + u * 8];

    float pos[2][2] = {{0.f, 0.f}, {0.f, 0.f}};
    float tot[2][2] = {{0.f, 0.f}, {0.f, 0.f}};

    for (int d = 0; d < npair; d++) {
        const int jt  = (it + d) & 31;
        const int cur = d & 1;
        if (d + 1 < npair) {
            const int j0n = ((it + d + 1) & 31) * 128;
            uint32_t bdst = sb + (cur ? SM_B0 : SM_B1);
#pragma unroll
            for (int t = 0; t < 8; t++) {
                int idx = tid + t * 256;
                int row = idx >> 4, c16 = idx & 15;
                cp16(bdst + row * ROWB + c16 * 16,
                     vt + (size_t)(j0n + row) * CC + c16 * 8);
            }
            cp_commit();
        }

        const uint32_t aB = sb + SM_A;
        const uint32_t bB = sb + (cur ? SM_B1 : SM_B0);
        const int j0 = jt * 128;

        if (d == 0)
            do_tile<true>(aB, bB, i0, j0, wm, wn, lane, rl, lab8s, pos, tot, scol);
        else
            do_tile<false>(aB, bB, i0, j0, wm, wn, lane, rl, lab8s, pos, tot, scol);

        __syncthreads();                    // scol complete
        if (d > 0 && tid < 128) {
            float p = scol[(0 * 128 + tid) * 2]     + scol[(1 * 128 + tid) * 2]
                    + scol[(2 * 128 + tid) * 2]     + scol[(3 * 128 + tid) * 2];
            float t = scol[(0 * 128 + tid) * 2 + 1] + scol[(1 * 128 + tid) * 2 + 1]
                    + scol[(2 * 128 + tid) * 2 + 1] + scol[(3 * 128 + tid) * 2 + 1];
            g_stage[((size_t)(b * 32 + jt) * NSLOT + 2 + (d - 1)) * 128 + tid]
                = make_float2(p, t);
        }
        cp_wait0();
        __syncthreads();                    // scol reads done; B buffer ready
    }

    // own-row sums -> slots 0 (wn=0) and 1 (wn=1)
#pragma unroll
    for (int mt = 0; mt < 2; mt++)
#pragma unroll
        for (int u = 0; u < 2; u++) {
            float p = pos[mt][u], t = tot[mt][u];
            p += __shfl_xor_sync(0xFFFFFFFF, p, 1);
            p += __shfl_xor_sync(0xFFFFFFFF, p, 2);
            t += __shfl_xor_sync(0xFFFFFFFF, t, 1);
            t += __shfl_xor_sync(0xFFFFFFFF, t, 2);
            if ((lane & 3) == 0) {
                int row = wm * 32 + mt * 16 + (lane >> 2) + u * 8;
                g_stage[((size_t)(b * 32 + it) * NSLOT + wn) * 128 + row]
                    = make_float2(p, t);
            }
        }
}

// ---------------------------------------------------------------------------
// Kernel D: per-row combine of staged partials + loss term + block partial
// ---------------------------------------------------------------------------
__global__ void k_final() {
    __shared__ float red[128];
    const int blk = blockIdx.x;           // (b*32 + jt)
    const int b = blk >> 5, jt = blk & 31;
    const int r = threadIdx.x;            // 128 threads, one row each
    const float2* st = g_stage + (size_t)blk * NSLOT * 128;

    float p = 0.f, t = 0.f;
    const int ns = (jt >= 16) ? NSLOT : (NSLOT - 1);
#pragma unroll 1
    for (int s = 0; s < ns; s++) {
        float2 v = st[s * 128 + r];
        p += v.x; t += v.y;
    }
    int i = b * NN + jt * 128 + r;
    int l = (int)g_lab8[i];
    int cnt = g_cnt[b * NLAB + l];
    float pm = p / (float)cnt;
    float nm = (t - p) / (float)(NN - cnt);
    red[r] = __logf((pm + nm) / pm);
    __syncthreads();
    if (r < 64) red[r] += red[r + 64];
    __syncthreads();
    if (r < 32) {
        float v = red[r] + red[r + 32];
#pragma unroll
        for (int o = 16; o > 0; o >>= 1) v += __shfl_xor_sync(0xFFFFFFFF, v, o);
        if (r == 0) g_part[blk] = v;
    }
}

// ---------------------------------------------------------------------------
// Kernel E: sum 256 partials -> mean
// ---------------------------------------------------------------------------
__global__ void k_loss(float* __restrict__ out) {
    __shared__ float red[256];
    int t = threadIdx.x;
    red[t] = g_part[t];
    __syncthreads();
    if (t < 128) red[t] += red[t + 128];
    __syncthreads();
    if (t < 64) red[t] += red[t + 64];
    __syncthreads();
    if (t < 32) {
        float v = red[t] + red[t + 32];
#pragma unroll
        for (int o = 16; o > 0; o >>= 1) v += __shfl_xor_sync(0xFFFFFFFF, v, o);
        if (t == 0) out[0] = v / (float)(BB * NN);
    }
}

// ---------------------------------------------------------------------------
extern "C" void kernel_launch(void* const* d_in, const int* in_sizes, int n_in,
                              void* d_out, int out_size) {
    const float* f   = (const float*)d_in[0];
    const int*   lab = (const int*)d_in[1];
    float*       out = (float*)d_out;

    cudaFuncSetAttribute(k_norm, cudaFuncAttributeMaxDynamicSharedMemorySize,
                         (128 * 129 + 128) * 4);
    cudaFuncSetAttribute(k_gram, cudaFuncAttributeMaxDynamicSharedMemorySize,
                         SMEM_DYN);

    k_labels<<<BB, 256>>>(lab);
    k_norm<<<dim3(NN / 128, BB), 256, (128 * 129 + 128) * 4>>>(f);
    k_gram<<<dim3(32, BB), 256, SMEM_DYN>>>();
    k_final<<<BB * 32, 128>>>();
    k_loss<<<1, 256>>>(out);
}

// round 7
// speedup vs baseline: 7.3628x; 1.0345x over previous
#include <cuda_runtime.h>
#include <cuda_bf16.h>
#include <math.h>
#include <stdint.h>

#define BB   8
#define CC   128
#define NN   4096
#define NLAB 16
// slots: 0,1 = own-row sums (wn=0/1); 2 + (d-1)*4 + wm = col partials, d=1..16
#define NSLOT 66

// ---------------------------------------------------------------------------
// Device scratch (no allocations allowed)
// ---------------------------------------------------------------------------
__device__ __nv_bfloat16 g_vt[BB * NN * CC];     // normalized (x sqrt(log2e)) [b][n][c]
__device__ unsigned char g_lab8[BB * NN];
__device__ int           g_cnt[BB * NLAB];
__device__ float2        g_stage[BB * 32 * NSLOT * 128];  // (pos, tot) partials
__device__ float         g_part[BB * 32];
__device__ unsigned int  g_ctr;

// ---------------------------------------------------------------------------
// smem layout for k_gram. Tile rows padded to 272B (conflict-free LDSM).
// ---------------------------------------------------------------------------
#define ROWB   272
#define TILEB  (128 * ROWB)          // 34816
#define SM_A   0
#define SM_B0  TILEB
#define SM_B1  (2 * TILEB)
#define SM_LAB (3 * TILEB)           // 4096 B labels
#define SMEM_DYN (SM_LAB + 4096)     // 108544 B -> 2 CTAs/SM

// ---------------------------------------------------------------------------
// PTX helpers (plain sm_80+ features)
// ---------------------------------------------------------------------------
__device__ __forceinline__ uint32_t s2u(const void* p) {
    return (uint32_t)__cvta_generic_to_shared(p);
}
__device__ __forceinline__ void cp16(uint32_t dst, const void* src) {
    asm volatile("cp.async.cg.shared.global [%0], [%1], 16;" :: "r"(dst), "l"(src) : "memory");
}
__device__ __forceinline__ void cp_commit() { asm volatile("cp.async.commit_group;" ::: "memory"); }
__device__ __forceinline__ void cp_wait0()  { asm volatile("cp.async.wait_group 0;" ::: "memory"); }

__device__ __forceinline__ void ldsm4(uint32_t* r, uint32_t addr) {
    asm volatile("ldmatrix.sync.aligned.m8n8.x4.shared.b16 {%0,%1,%2,%3}, [%4];"
                 : "=r"(r[0]), "=r"(r[1]), "=r"(r[2]), "=r"(r[3]) : "r"(addr));
}
__device__ __forceinline__ void mma16816(float* c, const uint32_t* a,
                                         uint32_t b0, uint32_t b1) {
    asm volatile(
        "mma.sync.aligned.m16n8k16.row.col.f32.bf16.bf16.f32 "
        "{%0,%1,%2,%3}, {%4,%5,%6,%7}, {%8,%9}, {%0,%1,%2,%3};"
        : "+f"(c[0]), "+f"(c[1]), "+f"(c[2]), "+f"(c[3])
        : "r"(a[0]), "r"(a[1]), "r"(a[2]), "r"(a[3]), "r"(b0), "r"(b1));
}
__device__ __forceinline__ float ex2(float x) {
    float y; asm("ex2.approx.f32 %0, %1;" : "=f"(y) : "f"(x)); return y;
}

// ---------------------------------------------------------------------------
// Kernel A: labels -> uint8 copy + per-cloud histogram (+ counter reset)
// ---------------------------------------------------------------------------
__global__ void k_labels(const int* __restrict__ labels) {
    __shared__ int hist[NLAB];
    int b = blockIdx.x;
    if (b == 0 && threadIdx.x == 0) g_ctr = 0;
    if (threadIdx.x < NLAB) hist[threadIdx.x] = 0;
    __syncthreads();
    for (int n = threadIdx.x; n < NN; n += blockDim.x) {
        int l = labels[b * NN + n];
        g_lab8[b * NN + n] = (unsigned char)l;
        atomicAdd(&hist[l], 1);
    }
    __syncthreads();
    if (threadIdx.x < NLAB) g_cnt[b * NLAB + threadIdx.x] = hist[threadIdx.x];
}

// ---------------------------------------------------------------------------
// Kernel B: normalize (x sqrt(log2e)) + transpose + bf16: g_vt[b][n][c]
// ---------------------------------------------------------------------------
__global__ void k_norm(const float* __restrict__ f) {
    extern __shared__ float ts[];               // [128][129] + rinv[128]
    float* rinv = ts + 128 * 129;
    int b = blockIdx.y, n0 = blockIdx.x * 128;
    const float* fb = f + (size_t)b * CC * NN;
    for (int idx = threadIdx.x; idx < 128 * 128; idx += 256) {
        int k = idx >> 7, n = idx & 127;
        ts[n * 129 + k] = fb[k * NN + n0 + n];
    }
    __syncthreads();
    if (threadIdx.x < 128) {
        float ss = 0.f;
#pragma unroll 8
        for (int k = 0; k < 128; k++) {
            float x = ts[threadIdx.x * 129 + k];
            ss = fmaf(x, x, ss);
        }
        rinv[threadIdx.x] = 1.2011224087864498f / fmaxf(sqrtf(ss), 1e-12f);
    }
    __syncthreads();
    __nv_bfloat162* o2 = (__nv_bfloat162*)g_vt;
    for (int idx = threadIdx.x; idx < 128 * 64; idx += 256) {
        int n = idx >> 6, c2 = idx & 63;
        float r = rinv[n];
        float v0 = ts[n * 129 + 2 * c2] * r;
        float v1 = ts[n * 129 + 2 * c2 + 1] * r;
        o2[((size_t)b * NN + n0 + n) * 64 + c2] = __floats2bfloat162_rn(v0, v1);
    }
}

// ---------------------------------------------------------------------------
// One 128x128 tile: MMA + exp + row sums (registers) + col sums -> g_stage
// ---------------------------------------------------------------------------
template <bool DIAG>
__device__ __forceinline__ void do_tile(
    uint32_t aB, uint32_t bB, int i0, int j0,
    int wm, int wn, int lane,
    const int rl[2][2], const unsigned char* __restrict__ lab8s,
    float pos[2][2], float tot[2][2], float2* __restrict__ cstage)
{
    const int lrow = lane & 15;
    const int lkof = (lane >> 4) << 3;

#pragma unroll
    for (int h = 0; h < 2; h++) {
        float acc[2][4][4];
#pragma unroll
        for (int mt = 0; mt < 2; mt++)
#pragma unroll
            for (int nt = 0; nt < 4; nt++)
#pragma unroll
                for (int r = 0; r < 4; r++) acc[mt][nt][r] = 0.f;

#pragma unroll
        for (int ks = 0; ks < 8; ks++) {
            const int k0 = ks * 16;
            uint32_t a[2][4], bq[2][4];
#pragma unroll
            for (int mt = 0; mt < 2; mt++) {
                int row = wm * 32 + mt * 16 + lrow;
                ldsm4(a[mt], aB + row * ROWB + (k0 + lkof) * 2);
            }
#pragma unroll
            for (int q = 0; q < 2; q++) {
                int row = wn * 64 + h * 32 + q * 16 + lrow;
                ldsm4(bq[q], bB + row * ROWB + (k0 + lkof) * 2);
            }
#pragma unroll
            for (int mt = 0; mt < 2; mt++)
#pragma unroll
                for (int q = 0; q < 2; q++) {
                    mma16816(acc[mt][2 * q],     a[mt], bq[q][0], bq[q][2]);
                    mma16816(acc[mt][2 * q + 1], a[mt], bq[q][1], bq[q][3]);
                }
        }

        int cl0[4], cl1[4];
#pragma unroll
        for (int nt = 0; nt < 4; nt++) {
            int jj = j0 + wn * 64 + h * 32 + nt * 8 + (lane & 3) * 2;
            cl0[nt] = (int)lab8s[jj];
            cl1[nt] = (int)lab8s[jj + 1];
        }

        float cpos[4][2], ctot[4][2];
        if (!DIAG) {
#pragma unroll
            for (int nt = 0; nt < 4; nt++) {
                cpos[nt][0] = cpos[nt][1] = 0.f;
                ctot[nt][0] = ctot[nt][1] = 0.f;
            }
        }

#pragma unroll
        for (int mt = 0; mt < 2; mt++)
#pragma unroll
            for (int u = 0; u < 2; u++) {
                const int rlab = rl[mt][u];
                float tsum = 0.f, psum = 0.f;
#pragma unroll
                for (int nt = 0; nt < 4; nt++) {
                    float e0 = ex2(acc[mt][nt][2 * u]);
                    float e1 = ex2(acc[mt][nt][2 * u + 1]);
                    if (DIAG) {
                        const int gi = i0 + wm * 32 + mt * 16 + (lane >> 2) + u * 8;
                        const int gj = j0 + wn * 64 + h * 32 + nt * 8 + (lane & 3) * 2;
                        if (gi == gj)     e0 = 0.f;
                        if (gi == gj + 1) e1 = 0.f;
                    }
                    const bool m0 = (cl0[nt] == rlab);
                    const bool m1 = (cl1[nt] == rlab);
                    tsum += e0 + e1;
                    if (m0) psum += e0;
                    if (m1) psum += e1;
                    if (!DIAG) {
                        ctot[nt][0] += e0;
                        ctot[nt][1] += e1;
                        if (m0) cpos[nt][0] += e0;
                        if (m1) cpos[nt][1] += e1;
                    }
                }
                tot[mt][u] += tsum;
                pos[mt][u] += psum;
            }

        if (!DIAG) {
            // reduce col partials over the 8 lanes sharing (lane&3); direct STG
#pragma unroll
            for (int nt = 0; nt < 4; nt++)
#pragma unroll
                for (int e = 0; e < 2; e++) {
                    float cp = cpos[nt][e], ct = ctot[nt][e];
                    cp += __shfl_xor_sync(0xFFFFFFFF, cp, 4);
                    cp += __shfl_xor_sync(0xFFFFFFFF, cp, 8);
                    cp += __shfl_xor_sync(0xFFFFFFFF, cp, 16);
                    ct += __shfl_xor_sync(0xFFFFFFFF, ct, 4);
                    ct += __shfl_xor_sync(0xFFFFFFFF, ct, 8);
                    ct += __shfl_xor_sync(0xFFFFFFFF, ct, 16);
                    if (lane < 4) {
                        int col = wn * 64 + h * 32 + nt * 8 + lane * 2 + e;
                        cstage[col] = make_float2(cp, ct);
                    }
                }
        }
    }
}

// ---------------------------------------------------------------------------
// Kernel C: symmetric HMMA Gram. CTA it streams jt=(it+d)&31, d=0..15/16.
// ---------------------------------------------------------------------------
__global__ __launch_bounds__(256, 2) void k_gram() {
    extern __shared__ char sm[];
    const uint32_t sb = s2u(sm);
    unsigned char* lab8s = (unsigned char*)(sm + SM_LAB);

    const int b    = blockIdx.y;
    const int it   = blockIdx.x;
    const int i0   = it * 128;
    const int tid  = threadIdx.x;
    const int wid  = tid >> 5;
    const int lane = tid & 31;
    const int wm   = wid & 3;
    const int wn   = wid >> 2;
    const int npair = (it < 16) ? 17 : 16;

    const __nv_bfloat16* vt = g_vt + (size_t)b * NN * CC;

#pragma unroll
    for (int t = 0; t < 8; t++) {
        int idx = tid + t * 256;
        int row = idx >> 4, c16 = idx & 15;
        cp16(sb + SM_A + row * ROWB + c16 * 16,
             vt + (size_t)(i0 + row) * CC + c16 * 8);
        cp16(sb + SM_B0 + row * ROWB + c16 * 16,
             vt + (size_t)(i0 + row) * CC + c16 * 8);
    }
    cp16(sb + SM_LAB + tid * 16, g_lab8 + (size_t)b * NN + tid * 16);
    cp_commit();
    cp_wait0();
    __syncthreads();

    int rl[2][2];
#pragma unroll
    for (int mt = 0; mt < 2; mt++)
#pragma unroll
        for (int u = 0; u < 2; u++)
            rl[mt][u] = (int)lab8s[i0 + wm * 32 + mt * 16 + (lane >> 2) + u * 8];

    float pos[2][2] = {{0.f, 0.f}, {0.f, 0.f}};
    float tot[2][2] = {{0.f, 0.f}, {0.f, 0.f}};

    for (int d = 0; d < npair; d++) {
        const int jt  = (it + d) & 31;
        const int cur = d & 1;
        if (d + 1 < npair) {
            const int j0n = ((it + d + 1) & 31) * 128;
            uint32_t bdst = sb + (cur ? SM_B0 : SM_B1);
#pragma unroll
            for (int t = 0; t < 8; t++) {
                int idx = tid + t * 256;
                int row = idx >> 4, c16 = idx & 15;
                cp16(bdst + row * ROWB + c16 * 16,
                     vt + (size_t)(j0n + row) * CC + c16 * 8);
            }
            cp_commit();
        }

        const uint32_t aB = sb + SM_A;
        const uint32_t bB = sb + (cur ? SM_B1 : SM_B0);
        const int j0 = jt * 128;

        if (d == 0) {
            do_tile<true>(aB, bB, i0, j0, wm, wn, lane, rl, lab8s, pos, tot,
                          (float2*)0);
        } else {
            float2* cstage = g_stage
                + ((size_t)(b * 32 + jt) * NSLOT + 2 + (d - 1) * 4 + wm) * 128;
            do_tile<false>(aB, bB, i0, j0, wm, wn, lane, rl, lab8s, pos, tot,
                           cstage);
        }

        cp_wait0();
        __syncthreads();
    }

    // own-row sums -> slots 0 (wn=0) and 1 (wn=1)
#pragma unroll
    for (int mt = 0; mt < 2; mt++)
#pragma unroll
        for (int u = 0; u < 2; u++) {
            float p = pos[mt][u], t = tot[mt][u];
            p += __shfl_xor_sync(0xFFFFFFFF, p, 1);
            p += __shfl_xor_sync(0xFFFFFFFF, p, 2);
            t += __shfl_xor_sync(0xFFFFFFFF, t, 1);
            t += __shfl_xor_sync(0xFFFFFFFF, t, 2);
            if ((lane & 3) == 0) {
                int row = wm * 32 + mt * 16 + (lane >> 2) + u * 8;
                g_stage[((size_t)(b * 32 + it) * NSLOT + wn) * 128 + row]
                    = make_float2(p, t);
            }
        }
}

// ---------------------------------------------------------------------------
// Kernel D: combine staged partials, per-row loss, block partial, final sum.
// ---------------------------------------------------------------------------
__global__ void k_final(float* __restrict__ out) {
    __shared__ float red[128];
    __shared__ int amLast;
    const int blk = blockIdx.x;           // (b*32 + jt)
    const int b = blk >> 5, jt = blk & 31;
    const int r = threadIdx.x;            // 128 threads, one row each
    const float2* st = g_stage + (size_t)blk * NSLOT * 128;

    float2 v0 = st[r];
    float2 v1 = st[128 + r];
    float p = v0.x + v1.x, t = v0.y + v1.y;
    // d = 1..15 always valid (60 slots)
#pragma unroll
    for (int s = 2; s < 62; s++) {
        float2 v = st[s * 128 + r];
        p += v.x; t += v.y;
    }
    // d = 16 valid iff jt >= 16 (sender it = jt-16 < 16)
    if (jt >= 16) {
#pragma unroll
        for (int s = 62; s < 66; s++) {
            float2 v = st[s * 128 + r];
            p += v.x; t += v.y;
        }
    }

    int i = b * NN + jt * 128 + r;
    int l = (int)g_lab8[i];
    int cnt = g_cnt[b * NLAB + l];
    float pm = p / (float)cnt;
    float nm = (t - p) / (float)(NN - cnt);
    red[r] = __logf((pm + nm) / pm);
    __syncthreads();
    if (r < 64) red[r] += red[r + 64];
    __syncthreads();
    if (r < 32) {
        float v = red[r] + red[r + 32];
#pragma unroll
        for (int o = 16; o > 0; o >>= 1) v += __shfl_xor_sync(0xFFFFFFFF, v, o);
        if (r == 0) {
            g_part[blk] = v;
            __threadfence();
            amLast = (atomicAdd(&g_ctr, 1u) == (unsigned)(BB * 32 - 1));
        }
    }
    __syncthreads();
    if (amLast) {
        float s = (r < 128) ? g_part[r] + g_part[r + 128] : 0.f;
        red[r] = s;
        __syncthreads();
        if (r < 64) red[r] += red[r + 64];
        __syncthreads();
        if (r < 32) {
            float v = red[r] + red[r + 32];
#pragma unroll
            for (int o = 16; o > 0; o >>= 1) v += __shfl_xor_sync(0xFFFFFFFF, v, o);
            if (r == 0) out[0] = v / (float)(BB * NN);
        }
    }
}

// ---------------------------------------------------------------------------
extern "C" void kernel_launch(void* const* d_in, const int* in_sizes, int n_in,
                              void* d_out, int out_size) {
    const float* f   = (const float*)d_in[0];
    const int*   lab = (const int*)d_in[1];
    float*       out = (float*)d_out;

    cudaFuncSetAttribute(k_norm, cudaFuncAttributeMaxDynamicSharedMemorySize,
                         (128 * 129 + 128) * 4);
    cudaFuncSetAttribute(k_gram, cudaFuncAttributeMaxDynamicSharedMemorySize,
                         SMEM_DYN);

    k_labels<<<BB, 256>>>(lab);
    k_norm<<<dim3(NN / 128, BB), 256, (128 * 129 + 128) * 4>>>(f);
    k_gram<<<dim3(32, BB), 256, SMEM_DYN>>>();
    k_final<<<BB * 32, 128>>>(out);
}

// round 8
// speedup vs baseline: 7.7512x; 1.0527x over previous
#include <cuda_runtime.h>
#include <cuda_bf16.h>
#include <math.h>
#include <stdint.h>

#define BB   8
#define CC   128
#define NN   4096
#define NLAB 16
// slots: 0,1 = own-row sums (wn=0/1); 2 + (d-1)*4 + wm = col partials, d=1..16
#define NSLOT 66

// ---------------------------------------------------------------------------
// Device scratch (no allocations allowed)
// ---------------------------------------------------------------------------
__device__ __nv_bfloat16 g_vt[BB * NN * CC];     // normalized (x sqrt(log2e)) [b][n][c]
__device__ unsigned char g_lab8[BB * NN];
__device__ int           g_cnt[BB * NLAB];
__device__ float2        g_stage[BB * 32 * NSLOT * 128];  // (pos, tot) partials
__device__ float         g_part[BB * 32];
__device__ unsigned int  g_ctr;

// ---------------------------------------------------------------------------
// smem layout for k_gram. Tile rows padded to 272B (conflict-free LDSM).
// ---------------------------------------------------------------------------
#define ROWB   272
#define TILEB  (128 * ROWB)          // 34816
#define SM_A   0
#define SM_B0  TILEB
#define SM_B1  (2 * TILEB)
#define SM_LAB (3 * TILEB)           // 4096 B labels
#define SMEM_DYN (SM_LAB + 4096)     // 108544 B -> 2 CTAs/SM

// ---------------------------------------------------------------------------
// PTX helpers (plain sm_80+ features)
// ---------------------------------------------------------------------------
__device__ __forceinline__ uint32_t s2u(const void* p) {
    return (uint32_t)__cvta_generic_to_shared(p);
}
__device__ __forceinline__ void cp16(uint32_t dst, const void* src) {
    asm volatile("cp.async.cg.shared.global [%0], [%1], 16;" :: "r"(dst), "l"(src) : "memory");
}
__device__ __forceinline__ void cp_commit() { asm volatile("cp.async.commit_group;" ::: "memory"); }
__device__ __forceinline__ void cp_wait0()  { asm volatile("cp.async.wait_group 0;" ::: "memory"); }

__device__ __forceinline__ void ldsm4(uint32_t* r, uint32_t addr) {
    asm volatile("ldmatrix.sync.aligned.m8n8.x4.shared.b16 {%0,%1,%2,%3}, [%4];"
                 : "=r"(r[0]), "=r"(r[1]), "=r"(r[2]), "=r"(r[3]) : "r"(addr));
}
__device__ __forceinline__ void mma16816(float* c, const uint32_t* a,
                                         uint32_t b0, uint32_t b1) {
    asm volatile(
        "mma.sync.aligned.m16n8k16.row.col.f32.bf16.bf16.f32 "
        "{%0,%1,%2,%3}, {%4,%5,%6,%7}, {%8,%9}, {%0,%1,%2,%3};"
        : "+f"(c[0]), "+f"(c[1]), "+f"(c[2]), "+f"(c[3])
        : "r"(a[0]), "r"(a[1]), "r"(a[2]), "r"(a[3]), "r"(b0), "r"(b1));
}
__device__ __forceinline__ float ex2(float x) {
    float y; asm("ex2.approx.f32 %0, %1;" : "=f"(y) : "f"(x)); return y;
}

// ---------------------------------------------------------------------------
// Kernel A: labels -> uint8 copy + per-cloud histogram (+ counter reset)
// ---------------------------------------------------------------------------
__global__ void k_labels(const int* __restrict__ labels) {
    __shared__ int hist[NLAB];
    int b = blockIdx.x;
    if (b == 0 && threadIdx.x == 0) g_ctr = 0;
    if (threadIdx.x < NLAB) hist[threadIdx.x] = 0;
    __syncthreads();
    for (int n = threadIdx.x; n < NN; n += blockDim.x) {
        int l = labels[b * NN + n];
        g_lab8[b * NN + n] = (unsigned char)l;
        atomicAdd(&hist[l], 1);
    }
    __syncthreads();
    if (threadIdx.x < NLAB) g_cnt[b * NLAB + threadIdx.x] = hist[threadIdx.x];
}

// ---------------------------------------------------------------------------
// Kernel B: normalize (x sqrt(log2e)) + transpose + bf16: g_vt[b][n][c]
// ---------------------------------------------------------------------------
__global__ void k_norm(const float* __restrict__ f) {
    extern __shared__ float ts[];               // [128][129] + rinv[128]
    float* rinv = ts + 128 * 129;
    int b = blockIdx.y, n0 = blockIdx.x * 128;
    const float* fb = f + (size_t)b * CC * NN;
    for (int idx = threadIdx.x; idx < 128 * 128; idx += 256) {
        int k = idx >> 7, n = idx & 127;
        ts[n * 129 + k] = fb[k * NN + n0 + n];
    }
    __syncthreads();
    if (threadIdx.x < 128) {
        float ss = 0.f;
#pragma unroll 8
        for (int k = 0; k < 128; k++) {
            float x = ts[threadIdx.x * 129 + k];
            ss = fmaf(x, x, ss);
        }
        rinv[threadIdx.x] = 1.2011224087864498f / fmaxf(sqrtf(ss), 1e-12f);
    }
    __syncthreads();
    __nv_bfloat162* o2 = (__nv_bfloat162*)g_vt;
    for (int idx = threadIdx.x; idx < 128 * 64; idx += 256) {
        int n = idx >> 6, c2 = idx & 63;
        float r = rinv[n];
        float v0 = ts[n * 129 + 2 * c2] * r;
        float v1 = ts[n * 129 + 2 * c2 + 1] * r;
        o2[((size_t)b * NN + n0 + n) * 64 + c2] = __floats2bfloat162_rn(v0, v1);
    }
}

// ---------------------------------------------------------------------------
// One 128x128 tile, full 32x64 warp strip (A-fragments reused across cols).
// MMA + exp + row sums (registers) + col sums -> g_stage (direct STG).
// ---------------------------------------------------------------------------
template <bool DIAG>
__device__ __forceinline__ void do_tile(
    uint32_t aB, uint32_t bB, int i0, int j0,
    int wm, int wn, int lane,
    const int rl[2][2], const unsigned char* __restrict__ lab8s,
    float pos[2][2], float tot[2][2], float2* __restrict__ cstage)
{
    const int lrow = lane & 15;
    const int lkof = (lane >> 4) << 3;

    float acc[2][8][4];
#pragma unroll
    for (int mt = 0; mt < 2; mt++)
#pragma unroll
        for (int nt = 0; nt < 8; nt++)
#pragma unroll
            for (int r = 0; r < 4; r++) acc[mt][nt][r] = 0.f;

#pragma unroll
    for (int ks = 0; ks < 8; ks++) {
        const int k0 = ks * 16;
        uint32_t a[2][4], bq[4][4];
#pragma unroll
        for (int mt = 0; mt < 2; mt++) {
            int row = wm * 32 + mt * 16 + lrow;
            ldsm4(a[mt], aB + row * ROWB + (k0 + lkof) * 2);
        }
#pragma unroll
        for (int q = 0; q < 4; q++) {
            int row = wn * 64 + q * 16 + lrow;
            ldsm4(bq[q], bB + row * ROWB + (k0 + lkof) * 2);
        }
#pragma unroll
        for (int mt = 0; mt < 2; mt++)
#pragma unroll
            for (int q = 0; q < 4; q++) {
                mma16816(acc[mt][2 * q],     a[mt], bq[q][0], bq[q][2]);
                mma16816(acc[mt][2 * q + 1], a[mt], bq[q][1], bq[q][3]);
            }
    }

    // epilogue in two 4-nt groups (caps live col-partial registers)
#pragma unroll
    for (int g = 0; g < 2; g++) {
        int cl0[4], cl1[4];
#pragma unroll
        for (int n4 = 0; n4 < 4; n4++) {
            int jj = j0 + wn * 64 + (g * 4 + n4) * 8 + (lane & 3) * 2;
            cl0[n4] = (int)lab8s[jj];
            cl1[n4] = (int)lab8s[jj + 1];
        }

        float cpos[4][2], ctot[4][2];
        if (!DIAG) {
#pragma unroll
            for (int n4 = 0; n4 < 4; n4++) {
                cpos[n4][0] = cpos[n4][1] = 0.f;
                ctot[n4][0] = ctot[n4][1] = 0.f;
            }
        }

#pragma unroll
        for (int mt = 0; mt < 2; mt++)
#pragma unroll
            for (int u = 0; u < 2; u++) {
                const int rlab = rl[mt][u];
                float tsum = 0.f, psum = 0.f;
#pragma unroll
                for (int n4 = 0; n4 < 4; n4++) {
                    const int nt = g * 4 + n4;
                    float e0 = ex2(acc[mt][nt][2 * u]);
                    float e1 = ex2(acc[mt][nt][2 * u + 1]);
                    if (DIAG) {
                        const int gi = i0 + wm * 32 + mt * 16 + (lane >> 2) + u * 8;
                        const int gj = j0 + wn * 64 + nt * 8 + (lane & 3) * 2;
                        if (gi == gj)     e0 = 0.f;
                        if (gi == gj + 1) e1 = 0.f;
                    }
                    const bool m0 = (cl0[n4] == rlab);
                    const bool m1 = (cl1[n4] == rlab);
                    tsum += e0 + e1;
                    if (m0) psum += e0;
                    if (m1) psum += e1;
                    if (!DIAG) {
                        ctot[n4][0] += e0;
                        ctot[n4][1] += e1;
                        if (m0) cpos[n4][0] += e0;
                        if (m1) cpos[n4][1] += e1;
                    }
                }
                tot[mt][u] += tsum;
                pos[mt][u] += psum;
            }

        if (!DIAG) {
#pragma unroll
            for (int n4 = 0; n4 < 4; n4++)
#pragma unroll
                for (int e = 0; e < 2; e++) {
                    float cp = cpos[n4][e], ct = ctot[n4][e];
                    cp += __shfl_xor_sync(0xFFFFFFFF, cp, 4);
                    cp += __shfl_xor_sync(0xFFFFFFFF, cp, 8);
                    cp += __shfl_xor_sync(0xFFFFFFFF, cp, 16);
                    ct += __shfl_xor_sync(0xFFFFFFFF, ct, 4);
                    ct += __shfl_xor_sync(0xFFFFFFFF, ct, 8);
                    ct += __shfl_xor_sync(0xFFFFFFFF, ct, 16);
                    if (lane < 4) {
                        int col = wn * 64 + (g * 4 + n4) * 8 + lane * 2 + e;
                        cstage[col] = make_float2(cp, ct);
                    }
                }
        }
    }
}

// ---------------------------------------------------------------------------
// Kernel C: symmetric HMMA Gram. CTA it streams jt=(it+d)&31, d=0..15/16.
// ---------------------------------------------------------------------------
__global__ __launch_bounds__(256, 2) void k_gram() {
    extern __shared__ char sm[];
    const uint32_t sb = s2u(sm);
    unsigned char* lab8s = (unsigned char*)(sm + SM_LAB);

    const int b    = blockIdx.y;
    const int it   = blockIdx.x;
    const int i0   = it * 128;
    const int tid  = threadIdx.x;
    const int wid  = tid >> 5;
    const int lane = tid & 31;
    const int wm   = wid & 3;
    const int wn   = wid >> 2;
    const int npair = (it < 16) ? 17 : 16;

    const __nv_bfloat16* vt = g_vt + (size_t)b * NN * CC;

#pragma unroll
    for (int t = 0; t < 8; t++) {
        int idx = tid + t * 256;
        int row = idx >> 4, c16 = idx & 15;
        cp16(sb + SM_A + row * ROWB + c16 * 16,
             vt + (size_t)(i0 + row) * CC + c16 * 8);
        cp16(sb + SM_B0 + row * ROWB + c16 * 16,
             vt + (size_t)(i0 + row) * CC + c16 * 8);
    }
    cp16(sb + SM_LAB + tid * 16, g_lab8 + (size_t)b * NN + tid * 16);
    cp_commit();
    cp_wait0();
    __syncthreads();

    int rl[2][2];
#pragma unroll
    for (int mt = 0; mt < 2; mt++)
#pragma unroll
        for (int u = 0; u < 2; u++)
            rl[mt][u] = (int)lab8s[i0 + wm * 32 + mt * 16 + (lane >> 2) + u * 8];

    float pos[2][2] = {{0.f, 0.f}, {0.f, 0.f}};
    float tot[2][2] = {{0.f, 0.f}, {0.f, 0.f}};

    for (int d = 0; d < npair; d++) {
        const int jt  = (it + d) & 31;
        const int cur = d & 1;
        if (d + 1 < npair) {
            const int j0n = ((it + d + 1) & 31) * 128;
            uint32_t bdst = sb + (cur ? SM_B0 : SM_B1);
#pragma unroll
            for (int t = 0; t < 8; t++) {
                int idx = tid + t * 256;
                int row = idx >> 4, c16 = idx & 15;
                cp16(bdst + row * ROWB + c16 * 16,
                     vt + (size_t)(j0n + row) * CC + c16 * 8);
            }
            cp_commit();
        }

        const uint32_t aB = sb + SM_A;
        const uint32_t bB = sb + (cur ? SM_B1 : SM_B0);
        const int j0 = jt * 128;

        if (d == 0) {
            do_tile<true>(aB, bB, i0, j0, wm, wn, lane, rl, lab8s, pos, tot,
                          (float2*)0);
        } else {
            float2* cstage = g_stage
                + ((size_t)(b * 32 + jt) * NSLOT + 2 + (d - 1) * 4 + wm) * 128;
            do_tile<false>(aB, bB, i0, j0, wm, wn, lane, rl, lab8s, pos, tot,
                           cstage);
        }

        cp_wait0();
        __syncthreads();
    }

    // own-row sums -> slots 0 (wn=0) and 1 (wn=1)
#pragma unroll
    for (int mt = 0; mt < 2; mt++)
#pragma unroll
        for (int u = 0; u < 2; u++) {
            float p = pos[mt][u], t = tot[mt][u];
            p += __shfl_xor_sync(0xFFFFFFFF, p, 1);
            p += __shfl_xor_sync(0xFFFFFFFF, p, 2);
            t += __shfl_xor_sync(0xFFFFFFFF, t, 1);
            t += __shfl_xor_sync(0xFFFFFFFF, t, 2);
            if ((lane & 3) == 0) {
                int row = wm * 32 + mt * 16 + (lane >> 2) + u * 8;
                g_stage[((size_t)(b * 32 + it) * NSLOT + wn) * 128 + row]
                    = make_float2(p, t);
            }
        }
}

// ---------------------------------------------------------------------------
// Kernel D: combine staged partials (512 thr: 4 slot-stripes per row),
// per-row loss, block partial, fused final reduction (last block).
// ---------------------------------------------------------------------------
__global__ void k_final(float* __restrict__ out) {
    __shared__ float sp4[4][128], st4[4][128];
    __shared__ float red[512];
    __shared__ int amLast;
    const int blk = blockIdx.x;           // (b*32 + jt)
    const int b = blk >> 5, jt = blk & 31;
    const int t = threadIdx.x;            // 512 threads
    const int r = t & 127;                // row
    const int q = t >> 7;                 // slot stripe 0..3
    const float2* stg = g_stage + (size_t)blk * NSLOT * 128;

    float p = 0.f, tt = 0.f;
#pragma unroll
    for (int s = q; s < 62; s += 4) {     // strided: high MLP, disjoint slots
        float2 v = stg[s * 128 + r];
        p += v.x; tt += v.y;
    }
    if (jt >= 16) {                       // d=16 slots 62..65: one per stripe
        int s = (q < 2) ? (64 + q) : (60 + q);
        float2 v = stg[s * 128 + r];
        p += v.x; tt += v.y;
    }
    sp4[q][r] = p; st4[q][r] = tt;
    __syncthreads();

    if (t < 128) {
        float pp = sp4[0][t] + sp4[1][t] + sp4[2][t] + sp4[3][t];
        float tq = st4[0][t] + st4[1][t] + st4[2][t] + st4[3][t];
        int i = b * NN + jt * 128 + t;
        int l = (int)g_lab8[i];
        int cnt = g_cnt[b * NLAB + l];
        float pm = pp / (float)cnt;
        float nm = (tq - pp) / (float)(NN - cnt);
        red[t] = __logf((pm + nm) / pm);
    }
    __syncthreads();
    if (t < 64) red[t] += red[t + 64];
    __syncthreads();
    if (t < 32) {
        float v = red[t] + red[t + 32];
#pragma unroll
        for (int o = 16; o > 0; o >>= 1) v += __shfl_xor_sync(0xFFFFFFFF, v, o);
        if (t == 0) {
            g_part[blk] = v;
            __threadfence();
            amLast = (atomicAdd(&g_ctr, 1u) == (unsigned)(BB * 32 - 1));
        }
    }
    __syncthreads();
    if (amLast) {
        red[t] = (t < 256) ? g_part[t] : 0.f;
        __syncthreads();
        if (t < 128) red[t] += red[t + 128];
        __syncthreads();
        if (t < 64) red[t] += red[t + 64];
        __syncthreads();
        if (t < 32) {
            float v = red[t] + red[t + 32];
#pragma unroll
            for (int o = 16; o > 0; o >>= 1) v += __shfl_xor_sync(0xFFFFFFFF, v, o);
            if (t == 0) out[0] = v / (float)(BB * NN);
        }
    }
}

// ---------------------------------------------------------------------------
extern "C" void kernel_launch(void* const* d_in, const int* in_sizes, int n_in,
                              void* d_out, int out_size) {
    const float* f   = (const float*)d_in[0];
    const int*   lab = (const int*)d_in[1];
    float*       out = (float*)d_out;

    cudaFuncSetAttribute(k_norm, cudaFuncAttributeMaxDynamicSharedMemorySize,
                         (128 * 129 + 128) * 4);
    cudaFuncSetAttribute(k_gram, cudaFuncAttributeMaxDynamicSharedMemorySize,
                         SMEM_DYN);

    k_labels<<<BB, 256>>>(lab);
    k_norm<<<dim3(NN / 128, BB), 256, (128 * 129 + 128) * 4>>>(f);
    k_gram<<<dim3(32, BB), 256, SMEM_DYN>>>();
    k_final<<<BB * 32, 512>>>(out);
}

// round 9
// speedup vs baseline: 7.9308x; 1.0232x over previous
#include <cuda_runtime.h>
#include <cuda_bf16.h>
#include <math.h>
#include <stdint.h>

#define BB   8
#define CC   128
#define NN   4096
#define NLAB 16
// slots: 0,1 = own-row sums (wn=0/1); 2 + (d-1) = combined col sums, d=1..16
#define NSLOT 18

// ---------------------------------------------------------------------------
// Device scratch (no allocations allowed)
// ---------------------------------------------------------------------------
__device__ __nv_bfloat16 g_vt[BB * NN * CC];     // normalized (x sqrt(log2e)) [b][n][c]
__device__ unsigned char g_lab8[BB * NN];
__device__ int           g_cnt[BB * NLAB];
__device__ float2        g_stage[BB * 32 * NSLOT * 128];  // (pos, tot) partials
__device__ float         g_part[BB * 32];
__device__ unsigned int  g_ctr;

// ---------------------------------------------------------------------------
// smem layout for k_gram. Tile rows padded to 272B (conflict-free LDSM).
// ---------------------------------------------------------------------------
#define ROWB   272
#define TILEB  (128 * ROWB)          // 34816
#define SM_A   0
#define SM_B0  TILEB
#define SM_B1  (2 * TILEB)
#define SM_LAB (3 * TILEB)           // 4096 B labels
#define SM_CS  (SM_LAB + 4096)       // 4096 B col partials [4 wm][128 col][2]
#define SMEM_DYN (SM_CS + 4096)      // 112640 B -> 2 CTAs/SM

// ---------------------------------------------------------------------------
// PTX helpers (plain sm_80+ features)
// ---------------------------------------------------------------------------
__device__ __forceinline__ uint32_t s2u(const void* p) {
    return (uint32_t)__cvta_generic_to_shared(p);
}
__device__ __forceinline__ void cp16(uint32_t dst, const void* src) {
    asm volatile("cp.async.cg.shared.global [%0], [%1], 16;" :: "r"(dst), "l"(src) : "memory");
}
__device__ __forceinline__ void cp_commit() { asm volatile("cp.async.commit_group;" ::: "memory"); }
__device__ __forceinline__ void cp_wait0()  { asm volatile("cp.async.wait_group 0;" ::: "memory"); }

__device__ __forceinline__ void ldsm4(uint32_t* r, uint32_t addr) {
    asm volatile("ldmatrix.sync.aligned.m8n8.x4.shared.b16 {%0,%1,%2,%3}, [%4];"
                 : "=r"(r[0]), "=r"(r[1]), "=r"(r[2]), "=r"(r[3]) : "r"(addr));
}
__device__ __forceinline__ void mma16816(float* c, const uint32_t* a,
                                         uint32_t b0, uint32_t b1) {
    asm volatile(
        "mma.sync.aligned.m16n8k16.row.col.f32.bf16.bf16.f32 "
        "{%0,%1,%2,%3}, {%4,%5,%6,%7}, {%8,%9}, {%0,%1,%2,%3};"
        : "+f"(c[0]), "+f"(c[1]), "+f"(c[2]), "+f"(c[3])
        : "r"(a[0]), "r"(a[1]), "r"(a[2]), "r"(a[3]), "r"(b0), "r"(b1));
}
__device__ __forceinline__ float ex2(float x) {
    float y; asm("ex2.approx.f32 %0, %1;" : "=f"(y) : "f"(x)); return y;
}

// ---------------------------------------------------------------------------
// Kernel A: labels -> uint8 copy + per-cloud histogram (+ counter reset)
// ---------------------------------------------------------------------------
__global__ void k_labels(const int* __restrict__ labels) {
    __shared__ int hist[NLAB];
    int b = blockIdx.x;
    if (b == 0 && threadIdx.x == 0) g_ctr = 0;
    if (threadIdx.x < NLAB) hist[threadIdx.x] = 0;
    __syncthreads();
    for (int n = threadIdx.x; n < NN; n += blockDim.x) {
        int l = labels[b * NN + n];
        g_lab8[b * NN + n] = (unsigned char)l;
        atomicAdd(&hist[l], 1);
    }
    __syncthreads();
    if (threadIdx.x < NLAB) g_cnt[b * NLAB + threadIdx.x] = hist[threadIdx.x];
}

// ---------------------------------------------------------------------------
// Kernel B: normalize (x sqrt(log2e)) + transpose + bf16: g_vt[b][n][c]
// ---------------------------------------------------------------------------
__global__ void k_norm(const float* __restrict__ f) {
    extern __shared__ float ts[];               // [128][129] + rinv[128]
    float* rinv = ts + 128 * 129;
    int b = blockIdx.y, n0 = blockIdx.x * 128;
    const float* fb = f + (size_t)b * CC * NN;
    for (int idx = threadIdx.x; idx < 128 * 128; idx += 256) {
        int k = idx >> 7, n = idx & 127;
        ts[n * 129 + k] = fb[k * NN + n0 + n];
    }
    __syncthreads();
    if (threadIdx.x < 128) {
        float ss = 0.f;
#pragma unroll 8
        for (int k = 0; k < 128; k++) {
            float x = ts[threadIdx.x * 129 + k];
            ss = fmaf(x, x, ss);
        }
        rinv[threadIdx.x] = 1.2011224087864498f / fmaxf(sqrtf(ss), 1e-12f);
    }
    __syncthreads();
    __nv_bfloat162* o2 = (__nv_bfloat162*)g_vt;
    for (int idx = threadIdx.x; idx < 128 * 64; idx += 256) {
        int n = idx >> 6, c2 = idx & 63;
        float r = rinv[n];
        float v0 = ts[n * 129 + 2 * c2] * r;
        float v1 = ts[n * 129 + 2 * c2 + 1] * r;
        o2[((size_t)b * NN + n0 + n) * 64 + c2] = __floats2bfloat162_rn(v0, v1);
    }
}

// ---------------------------------------------------------------------------
// One 128x128 tile, full 32x64 warp strip (A-fragments reused across cols).
// MMA + exp + row sums (registers) + col sums -> scol (smem).
// ---------------------------------------------------------------------------
template <bool DIAG>
__device__ __forceinline__ void do_tile(
    uint32_t aB, uint32_t bB, int i0, int j0,
    int wm, int wn, int lane,
    const int rl[2][2], const unsigned char* __restrict__ lab8s,
    float pos[2][2], float tot[2][2], float* __restrict__ scol)
{
    const int lrow = lane & 15;
    const int lkof = (lane >> 4) << 3;

    float acc[2][8][4];
#pragma unroll
    for (int mt = 0; mt < 2; mt++)
#pragma unroll
        for (int nt = 0; nt < 8; nt++)
#pragma unroll
            for (int r = 0; r < 4; r++) acc[mt][nt][r] = 0.f;

#pragma unroll
    for (int ks = 0; ks < 8; ks++) {
        const int k0 = ks * 16;
        uint32_t a[2][4], bq[4][4];
#pragma unroll
        for (int mt = 0; mt < 2; mt++) {
            int row = wm * 32 + mt * 16 + lrow;
            ldsm4(a[mt], aB + row * ROWB + (k0 + lkof) * 2);
        }
#pragma unroll
        for (int q = 0; q < 4; q++) {
            int row = wn * 64 + q * 16 + lrow;
            ldsm4(bq[q], bB + row * ROWB + (k0 + lkof) * 2);
        }
#pragma unroll
        for (int mt = 0; mt < 2; mt++)
#pragma unroll
            for (int q = 0; q < 4; q++) {
                mma16816(acc[mt][2 * q],     a[mt], bq[q][0], bq[q][2]);
                mma16816(acc[mt][2 * q + 1], a[mt], bq[q][1], bq[q][3]);
            }
    }

    // epilogue in two 4-nt groups (caps live col-partial registers)
#pragma unroll
    for (int g = 0; g < 2; g++) {
        int cl0[4], cl1[4];
#pragma unroll
        for (int n4 = 0; n4 < 4; n4++) {
            int jj = j0 + wn * 64 + (g * 4 + n4) * 8 + (lane & 3) * 2;
            cl0[n4] = (int)lab8s[jj];
            cl1[n4] = (int)lab8s[jj + 1];
        }

        float cpos[4][2], ctot[4][2];
        if (!DIAG) {
#pragma unroll
            for (int n4 = 0; n4 < 4; n4++) {
                cpos[n4][0] = cpos[n4][1] = 0.f;
                ctot[n4][0] = ctot[n4][1] = 0.f;
            }
        }

#pragma unroll
        for (int mt = 0; mt < 2; mt++)
#pragma unroll
            for (int u = 0; u < 2; u++) {
                const int rlab = rl[mt][u];
                float tsum = 0.f, psum = 0.f;
#pragma unroll
                for (int n4 = 0; n4 < 4; n4++) {
                    const int nt = g * 4 + n4;
                    float e0 = ex2(acc[mt][nt][2 * u]);
                    float e1 = ex2(acc[mt][nt][2 * u + 1]);
                    if (DIAG) {
                        const int gi = i0 + wm * 32 + mt * 16 + (lane >> 2) + u * 8;
                        const int gj = j0 + wn * 64 + nt * 8 + (lane & 3) * 2;
                        if (gi == gj)     e0 = 0.f;
                        if (gi == gj + 1) e1 = 0.f;
                    }
                    const bool m0 = (cl0[n4] == rlab);
                    const bool m1 = (cl1[n4] == rlab);
                    tsum += e0 + e1;
                    if (m0) psum += e0;
                    if (m1) psum += e1;
                    if (!DIAG) {
                        ctot[n4][0] += e0;
                        ctot[n4][1] += e1;
                        if (m0) cpos[n4][0] += e0;
                        if (m1) cpos[n4][1] += e1;
                    }
                }
                tot[mt][u] += tsum;
                pos[mt][u] += psum;
            }

        if (!DIAG) {
            // reduce col partials over the 8 lanes sharing (lane&3) -> smem
#pragma unroll
            for (int n4 = 0; n4 < 4; n4++)
#pragma unroll
                for (int e = 0; e < 2; e++) {
                    float cp = cpos[n4][e], ct = ctot[n4][e];
                    cp += __shfl_xor_sync(0xFFFFFFFF, cp, 4);
                    cp += __shfl_xor_sync(0xFFFFFFFF, cp, 8);
                    cp += __shfl_xor_sync(0xFFFFFFFF, cp, 16);
                    ct += __shfl_xor_sync(0xFFFFFFFF, ct, 4);
                    ct += __shfl_xor_sync(0xFFFFFFFF, ct, 8);
                    ct += __shfl_xor_sync(0xFFFFFFFF, ct, 16);
                    if (lane < 4) {
                        int col = wn * 64 + (g * 4 + n4) * 8 + lane * 2 + e;
                        scol[(wm * 128 + col) * 2 + 0] = cp;
                        scol[(wm * 128 + col) * 2 + 1] = ct;
                    }
                }
        }
    }
}

// ---------------------------------------------------------------------------
// Kernel C: symmetric HMMA Gram. CTA it streams jt=(it+d)&31, d=0..15/16.
// ---------------------------------------------------------------------------
__global__ __launch_bounds__(256, 2) void k_gram() {
    extern __shared__ char sm[];
    const uint32_t sb = s2u(sm);
    unsigned char* lab8s = (unsigned char*)(sm + SM_LAB);
    float* scol = (float*)(sm + SM_CS);

    const int b    = blockIdx.y;
    const int it   = blockIdx.x;
    const int i0   = it * 128;
    const int tid  = threadIdx.x;
    const int wid  = tid >> 5;
    const int lane = tid & 31;
    const int wm   = wid & 3;
    const int wn   = wid >> 2;
    const int npair = (it < 16) ? 17 : 16;

    const __nv_bfloat16* vt = g_vt + (size_t)b * NN * CC;

#pragma unroll
    for (int t = 0; t < 8; t++) {
        int idx = tid + t * 256;
        int row = idx >> 4, c16 = idx & 15;
        cp16(sb + SM_A + row * ROWB + c16 * 16,
             vt + (size_t)(i0 + row) * CC + c16 * 8);
        cp16(sb + SM_B0 + row * ROWB + c16 * 16,
             vt + (size_t)(i0 + row) * CC + c16 * 8);
    }
    cp16(sb + SM_LAB + tid * 16, g_lab8 + (size_t)b * NN + tid * 16);
    cp_commit();
    cp_wait0();
    __syncthreads();

    int rl[2][2];
#pragma unroll
    for (int mt = 0; mt < 2; mt++)
#pragma unroll
        for (int u = 0; u < 2; u++)
            rl[mt][u] = (int)lab8s[i0 + wm * 32 + mt * 16 + (lane >> 2) + u * 8];

    float pos[2][2] = {{0.f, 0.f}, {0.f, 0.f}};
    float tot[2][2] = {{0.f, 0.f}, {0.f, 0.f}};

    for (int d = 0; d < npair; d++) {
        const int jt  = (it + d) & 31;
        const int cur = d & 1;
        if (d + 1 < npair) {
            const int j0n = ((it + d + 1) & 31) * 128;
            uint32_t bdst = sb + (cur ? SM_B0 : SM_B1);
#pragma unroll
            for (int t = 0; t < 8; t++) {
                int idx = tid + t * 256;
                int row = idx >> 4, c16 = idx & 15;
                cp16(bdst + row * ROWB + c16 * 16,
                     vt + (size_t)(j0n + row) * CC + c16 * 8);
            }
            cp_commit();
        }

        const uint32_t aB = sb + SM_A;
        const uint32_t bB = sb + (cur ? SM_B1 : SM_B0);
        const int j0 = jt * 128;

        if (d == 0)
            do_tile<true>(aB, bB, i0, j0, wm, wn, lane, rl, lab8s, pos, tot, scol);
        else
            do_tile<false>(aB, bB, i0, j0, wm, wn, lane, rl, lab8s, pos, tot, scol);

        __syncthreads();                    // scol complete
        if (d > 0 && tid < 128) {
            float p = scol[(0 * 128 + tid) * 2]     + scol[(1 * 128 + tid) * 2]
                    + scol[(2 * 128 + tid) * 2]     + scol[(3 * 128 + tid) * 2];
            float t = scol[(0 * 128 + tid) * 2 + 1] + scol[(1 * 128 + tid) * 2 + 1]
                    + scol[(2 * 128 + tid) * 2 + 1] + scol[(3 * 128 + tid) * 2 + 1];
            g_stage[((size_t)(b * 32 + jt) * NSLOT + 2 + (d - 1)) * 128 + tid]
                = make_float2(p, t);
        }
        cp_wait0();
        __syncthreads();                    // scol reads done; B buffer ready
    }

    // own-row sums -> slots 0 (wn=0) and 1 (wn=1)
#pragma unroll
    for (int mt = 0; mt < 2; mt++)
#pragma unroll
        for (int u = 0; u < 2; u++) {
            float p = pos[mt][u], t = tot[mt][u];
            p += __shfl_xor_sync(0xFFFFFFFF, p, 1);
            p += __shfl_xor_sync(0xFFFFFFFF, p, 2);
            t += __shfl_xor_sync(0xFFFFFFFF, t, 1);
            t += __shfl_xor_sync(0xFFFFFFFF, t, 2);
            if ((lane & 3) == 0) {
                int row = wm * 32 + mt * 16 + (lane >> 2) + u * 8;
                g_stage[((size_t)(b * 32 + it) * NSLOT + wn) * 128 + row]
                    = make_float2(p, t);
            }
        }
}

// ---------------------------------------------------------------------------
// Kernel D: combine staged partials (512 thr: 4 slot-stripes per row),
// per-row loss, block partial, fused final reduction (last block).
// ---------------------------------------------------------------------------
__global__ void k_final(float* __restrict__ out) {
    __shared__ float sp4[4][128], st4[4][128];
    __shared__ float red[512];
    __shared__ int amLast;
    const int blk = blockIdx.x;           // (b*32 + jt)
    const int b = blk >> 5, jt = blk & 31;
    const int t = threadIdx.x;            // 512 threads
    const int r = t & 127;                // row
    const int q = t >> 7;                 // slot stripe 0..3
    const float2* stg = g_stage + (size_t)blk * NSLOT * 128;

    float p = 0.f, tt = 0.f;
    // col slots 2..17, stripe q takes s = 2+q, 6+q, 10+q, 14+q
#pragma unroll
    for (int s = 2 + q; s < NSLOT; s += 4) {
        if (s == 17 && jt < 16) break;    // d=16 only valid for jt >= 16
        float2 v = stg[s * 128 + r];
        p += v.x; tt += v.y;
    }
    if (q < 2) {                          // own-row slots 0,1
        float2 v = stg[q * 128 + r];
        p += v.x; tt += v.y;
    }
    sp4[q][r] = p; st4[q][r] = tt;
    __syncthreads();

    if (t < 128) {
        float pp = sp4[0][t] + sp4[1][t] + sp4[2][t] + sp4[3][t];
        float tq = st4[0][t] + st4[1][t] + st4[2][t] + st4[3][t];
        int i = b * NN + jt * 128 + t;
        int l = (int)g_lab8[i];
        int cnt = g_cnt[b * NLAB + l];
        float pm = pp / (float)cnt;
        float nm = (tq - pp) / (float)(NN - cnt);
        red[t] = __logf((pm + nm) / pm);
    }
    __syncthreads();
    if (t < 64) red[t] += red[t + 64];
    __syncthreads();
    if (t < 32) {
        float v = red[t] + red[t + 32];
#pragma unroll
        for (int o = 16; o > 0; o >>= 1) v += __shfl_xor_sync(0xFFFFFFFF, v, o);
        if (t == 0) {
            g_part[blk] = v;
            __threadfence();
            amLast = (atomicAdd(&g_ctr, 1u) == (unsigned)(BB * 32 - 1));
        }
    }
    __syncthreads();
    if (amLast) {
        red[t] = (t < 256) ? g_part[t] : 0.f;
        __syncthreads();
        if (t < 128) red[t] += red[t + 128];
        __syncthreads();
        if (t < 64) red[t] += red[t + 64];
        __syncthreads();
        if (t < 32) {
            float v = red[t] + red[t + 32];
#pragma unroll
            for (int o = 16; o > 0; o >>= 1) v += __shfl_xor_sync(0xFFFFFFFF, v, o);
            if (t == 0) out[0] = v / (float)(BB * NN);
        }
    }
}

// ---------------------------------------------------------------------------
extern "C" void kernel_launch(void* const* d_in, const int* in_sizes, int n_in,
                              void* d_out, int out_size) {
    const float* f   = (const float*)d_in[0];
    const int*   lab = (const int*)d_in[1];
    float*       out = (float*)d_out;

    cudaFuncSetAttribute(k_norm, cudaFuncAttributeMaxDynamicSharedMemorySize,
                         (128 * 129 + 128) * 4);
    cudaFuncSetAttribute(k_gram, cudaFuncAttributeMaxDynamicSharedMemorySize,
                         SMEM_DYN);

    k_labels<<<BB, 256>>>(lab);
    k_norm<<<dim3(NN / 128, BB), 256, (128 * 129 + 128) * 4>>>(f);
    k_gram<<<dim3(32, BB), 256, SMEM_DYN>>>();
    k_final<<<BB * 32, 512>>>(out);
}